// round 2
// baseline (speedup 1.0000x reference)
#include <cuda_runtime.h>
#include <math.h>

// Problem constants
#define BB   32768
#define FF   1024
#define HH   512
#define EE   10
#define CC   10
#define KK   4
#define NC   32      // padded combined cols: [0..9]=q, [10..19]=k, [20..29]=v(k==0 only)

// Folded weights/biases (device globals: allocation-free scratch)
__device__ float g_Wc[KK * NC * FF];   // [k][c][f]
__device__ float g_bc[KK * NC];

// ---------------------------------------------------------------------------
// Kernel 1: fold Wc[k][c][:] = W{q,k,v}[k][c'] @ Wlin[k]   (per-k, per-f-chunk)
// grid (4, 32) x 128 threads, 64KB dynamic smem
// ---------------------------------------------------------------------------
__global__ void precompute_wc(const float* __restrict__ Wlin,
                              const float* __restrict__ Wq,
                              const float* __restrict__ Wk,
                              const float* __restrict__ Wv) {
    extern __shared__ float sW[];      // [32][512]
    const int k   = blockIdx.x;
    const int fc  = blockIdx.y;        // 0..31 (32 f's each)
    const int tid = threadIdx.x;       // 128

    // Stage the 32x512 small-projection weight block into smem
    for (int t = 0; t < 128; ++t) {
        int idx = tid + t * 128;       // 0..16383
        int c = idx >> 9;
        int j = idx & 511;
        float v = 0.f;
        if (c < 10)                       v = Wq[(k * 10 + c) * 512 + j];
        else if (c < 20)                  v = Wk[(k * 10 + (c - 10)) * 512 + j];
        else if (c < 30 && k == 0)        v = Wv[(c - 20) * 512 + j];
        sW[c * 512 + j] = v;
    }
    __syncthreads();

    const int f  = fc * 32 + (tid & 31);
    const int cg = tid >> 5;           // 0..3, 8 cols each
    float acc[8];
#pragma unroll
    for (int i = 0; i < 8; ++i) acc[i] = 0.f;

    const float* wl = Wlin + (size_t)k * HH * FF + f;
#pragma unroll 4
    for (int j = 0; j < 512; ++j) {
        float w = wl[(size_t)j * FF];  // coalesced across warp (f consecutive)
#pragma unroll
        for (int i = 0; i < 8; ++i)
            acc[i] += w * sW[(cg * 8 + i) * 512 + j];   // warp-broadcast LDS
    }
#pragma unroll
    for (int i = 0; i < 8; ++i)
        g_Wc[((k * NC) + cg * 8 + i) * FF + f] = acc[i];
}

// ---------------------------------------------------------------------------
// Kernel 2: folded biases  bc[k][c] = b{q,k,v}[k][c'] + W{q,k,v}[k][c'] . blin[k]
// ---------------------------------------------------------------------------
__global__ void precompute_bc(const float* __restrict__ blin,
                              const float* __restrict__ Wq, const float* __restrict__ bq,
                              const float* __restrict__ Wk, const float* __restrict__ bk,
                              const float* __restrict__ Wv, const float* __restrict__ bv) {
    int tid = threadIdx.x;             // 128 = 4k * 32c
    int k = tid >> 5;
    int c = tid & 31;
    const float* W = nullptr;
    float base = 0.f;
    if (c < 10)                { W = Wq + (k * 10 + c) * 512;        base = bq[k * 10 + c]; }
    else if (c < 20)           { W = Wk + (k * 10 + (c - 10)) * 512; base = bk[k * 10 + (c - 10)]; }
    else if (c < 30 && k == 0) { W = Wv + (c - 20) * 512;            base = bv[c - 20]; }
    float s = base;
    if (W) {
        const float* bl = blin + k * 512;
        for (int j = 0; j < 512; ++j) s += bl[j] * W[j];
        g_bc[k * 32 + c] = s;
    } else {
        g_bc[k * 32 + c] = 0.f;
    }
}

// ---------------------------------------------------------------------------
// Kernel 3: fused main. 256 blocks x 128 threads, 128 rows/block.
//  Phase 1: qkv[128][4][32] = w_k tile @ Wc[k]^T + bc   (smem-tiled fp32 GEMM)
//  Phase 2: per-row attention + softmax + logits + mean-softmax
// ---------------------------------------------------------------------------
#define SA_STRIDE 129   // sA[32][129]
#define SB_STRIDE 33    // sB[32][33]
#define SQ_STRIDE 129   // sQ[128][129]
#define SA_OFF 0
#define SB_OFF (32 * SA_STRIDE)
#define SQ_OFF (32 * SA_STRIDE + 32 * SB_STRIDE)
#define SMEM_FLOATS (SQ_OFF + 128 * SQ_STRIDE)

__global__ __launch_bounds__(128)
void fused_main(const float* __restrict__ w0, const float* __restrict__ w1,
                const float* __restrict__ w2, const float* __restrict__ w3,
                const float* __restrict__ Wfin, const float* __restrict__ bfin,
                float* __restrict__ out_outputs, float* __restrict__ out_attn) {
    extern __shared__ float sm[];
    float* sA = sm + SA_OFF;   // [f][row]   (32 x 129)
    float* sB = sm + SB_OFF;   // [f][col]   (32 x 33)
    float* sQ = sm + SQ_OFF;   // [row][k*32+c] (128 x 129)

    const int tid = threadIdx.x;
    const int b0  = blockIdx.x * 128;
    const int cg  = tid & 7;           // 8 col groups of 4
    const int rg  = tid >> 3;          // 16 row groups of 8
    const int c0  = cg * 4;
    const int r0  = rg * 8;

    // ---------------- Phase 1: qkv GEMM, one k at a time ----------------
    for (int k = 0; k < KK; ++k) {
        const float* wk = (k == 0) ? w0 : (k == 1) ? w1 : (k == 2) ? w2 : w3;

        float acc[8][4];
#pragma unroll
        for (int i = 0; i < 8; ++i)
#pragma unroll
            for (int j = 0; j < 4; ++j) acc[i][j] = 0.f;

        for (int ft = 0; ft < 32; ++ft) {
            const int fb = ft * 32;
            __syncthreads();   // previous tile fully consumed before overwrite

            // Load A tile: 128 rows x 32 f -> sA[f][row], float4 global loads
#pragma unroll
            for (int t = 0; t < 8; ++t) {
                int idx = tid + t * 128;         // 0..1023
                int row = idx >> 3;
                int f4  = idx & 7;
                const float4 v = *(const float4*)(wk + (size_t)(b0 + row) * FF + fb + f4 * 4);
                sA[(f4 * 4 + 0) * SA_STRIDE + row] = v.x;
                sA[(f4 * 4 + 1) * SA_STRIDE + row] = v.y;
                sA[(f4 * 4 + 2) * SA_STRIDE + row] = v.z;
                sA[(f4 * 4 + 3) * SA_STRIDE + row] = v.w;
            }
            // Load B tile: 32 cols x 32 f -> sB[f][c]
#pragma unroll
            for (int t = 0; t < 8; ++t) {
                int idx = tid + t * 128;         // 0..1023
                int f = idx & 31;
                int c = idx >> 5;
                sB[f * SB_STRIDE + c] = g_Wc[((size_t)k * NC + c) * FF + fb + f];
            }
            __syncthreads();

#pragma unroll 8
            for (int f = 0; f < 32; ++f) {
                float a[8], b[4];
#pragma unroll
                for (int i = 0; i < 8; ++i) a[i] = sA[f * SA_STRIDE + r0 + i];
#pragma unroll
                for (int j = 0; j < 4; ++j) b[j] = sB[f * SB_STRIDE + c0 + j];
#pragma unroll
                for (int i = 0; i < 8; ++i)
#pragma unroll
                    for (int j = 0; j < 4; ++j)
                        acc[i][j] += a[i] * b[j];
            }
        }

        // bias + store to sQ
#pragma unroll
        for (int j = 0; j < 4; ++j) {
            const float bias = g_bc[k * 32 + c0 + j];
#pragma unroll
            for (int i = 0; i < 8; ++i)
                sQ[(r0 + i) * SQ_STRIDE + k * 32 + c0 + j] = acc[i][j] + bias;
        }
    }
    __syncthreads();

    // ---------------- Phase 2: per-row attention ----------------
    {
        const int r = tid;
        const int b = b0 + r;
        const float* qr = &sQ[r * SQ_STRIDE];

        float q[KK][EE];
#pragma unroll
        for (int k = 0; k < KK; ++k)
#pragma unroll
            for (int e = 0; e < EE; ++e) q[k][e] = qr[k * 32 + e];

        float v0[EE];
#pragma unroll
        for (int m = 0; m < EE; ++m) v0[m] = qr[20 + m];

        float w0o[EE];
#pragma unroll
        for (int e = 0; e < EE; ++e) w0o[e] = 0.f;

        const float inv_sqrtE = 0.31622776601683794f;   // 1/sqrt(10)
        float* attn_row = out_attn + (size_t)b * (EE * EE);

#pragma unroll
        for (int l = 0; l < EE; ++l) {
            float kkv[KK];
#pragma unroll
            for (int k = 0; k < KK; ++k) kkv[k] = qr[k * 32 + 10 + l];

            float col[EE];
#pragma unroll
            for (int e = 0; e < EE; ++e)
                col[e] = (q[0][e] * kkv[0] + q[1][e] * kkv[1] +
                          q[2][e] * kkv[2] + q[3][e] * kkv[3]) * inv_sqrtE;

            float mx = col[0];
#pragma unroll
            for (int e = 1; e < EE; ++e) mx = fmaxf(mx, col[e]);
            float p[EE], s = 0.f;
#pragma unroll
            for (int e = 0; e < EE; ++e) { p[e] = __expf(col[e] - mx); s += p[e]; }
            const float is = 1.f / s;
#pragma unroll
            for (int e = 0; e < EE; ++e) {
                p[e] *= is;
                attn_row[e * EE + l] = p[e];     // attn[b][e][l]
                w0o[e] += p[e] * v0[l];          // att_out[b,0,e] accumulation over m=l
            }
        }

        float oacc[CC];
#pragma unroll
        for (int c = 0; c < CC; ++c) oacc[c] = 0.f;

#pragma unroll
        for (int k = 0; k < KK; ++k) {
            float lg[CC];
#pragma unroll
            for (int c = 0; c < CC; ++c) {
                float s2 = bfin[k * CC + c];
#pragma unroll
                for (int e = 0; e < EE; ++e)
                    s2 += w0o[e] * Wfin[k * CC * EE + c * EE + e];
                lg[c] = s2;
            }
            float mx = lg[0];
#pragma unroll
            for (int c = 1; c < CC; ++c) mx = fmaxf(mx, lg[c]);
            float p[CC], s = 0.f;
#pragma unroll
            for (int c = 0; c < CC; ++c) { p[c] = __expf(lg[c] - mx); s += p[c]; }
            const float is = 1.f / s;
#pragma unroll
            for (int c = 0; c < CC; ++c) oacc[c] += p[c] * is;
        }

        float* outr = out_outputs + (size_t)b * CC;
#pragma unroll
        for (int c = 0; c < CC; ++c) outr[c] = oacc[c] * 0.25f;
    }
}

// ---------------------------------------------------------------------------
extern "C" void kernel_launch(void* const* d_in, const int* in_sizes, int n_in,
                              void* d_out, int out_size) {
    const float* w0   = (const float*)d_in[0];
    const float* w1   = (const float*)d_in[1];
    const float* w2   = (const float*)d_in[2];
    const float* w3   = (const float*)d_in[3];
    const float* Wlin = (const float*)d_in[4];
    const float* blin = (const float*)d_in[5];
    const float* Wq   = (const float*)d_in[6];
    const float* bq   = (const float*)d_in[7];
    const float* Wk   = (const float*)d_in[8];
    const float* bk   = (const float*)d_in[9];
    const float* Wv   = (const float*)d_in[10];
    const float* bv   = (const float*)d_in[11];
    const float* Wfin = (const float*)d_in[12];
    const float* bfin = (const float*)d_in[13];

    float* out      = (float*)d_out;
    float* out_attn = out + (size_t)BB * CC;   // outputs first, then attn

    const int smem_wc   = 32 * 512 * 4;                 // 64 KB
    const int smem_main = SMEM_FLOATS * 4;              // ~85 KB
    cudaFuncSetAttribute(precompute_wc, cudaFuncAttributeMaxDynamicSharedMemorySize, smem_wc);
    cudaFuncSetAttribute(fused_main,    cudaFuncAttributeMaxDynamicSharedMemorySize, smem_main);

    precompute_wc<<<dim3(4, 32), 128, smem_wc>>>(Wlin, Wq, Wk, Wv);
    precompute_bc<<<1, 128>>>(blin, Wq, bq, Wk, bk, Wv, bv);
    fused_main<<<BB / 128, 128, smem_main>>>(w0, w1, w2, w3, Wfin, bfin, out, out_attn);
}

// round 3
// speedup vs baseline: 1.2348x; 1.2348x over previous
#include <cuda_runtime.h>
#include <math.h>

// Problem constants
#define BB   32768
#define FF   1024
#define HH   512
#define EE   10
#define CC   10
#define KK   4
#define NC   32      // padded combined cols: [0..9]=q, [10..19]=k, [20..29]=v(k==0 only)

// Folded weights/biases + reduction partials (device globals: allocation-free scratch)
__device__ float g_Wc[KK * NC * FF];        // [k][c][f]
__device__ float g_part[4 * KK * NC * FF];  // [js][k][c][f]
__device__ float g_bc[KK * NC];

// Packed fp32x2 FMA (sm_100+): d = a * b + d, two independent fp32 lanes
__device__ __forceinline__ void ffma2(unsigned long long& d,
                                      unsigned long long a,
                                      unsigned long long b) {
    asm("fma.rn.f32x2 %0, %1, %2, %0;" : "+l"(d) : "l"(a), "l"(b));
}

// ---------------------------------------------------------------------------
// Kernel 1a: partial fold over j-slices.
// grid (4 k, 32 fchunk, 4 jslice) = 512 blocks x 128 threads
// g_part[js][k][c][f] = sum_{j in slice} S[c][j] * Wlin[k][j][f]
// ---------------------------------------------------------------------------
__global__ void precompute_part(const float* __restrict__ Wlin,
                                const float* __restrict__ Wq,
                                const float* __restrict__ Wk,
                                const float* __restrict__ Wv) {
    __shared__ float sS[32 * 128];     // [c][j-slice]
    const int k   = blockIdx.x;
    const int fc  = blockIdx.y;
    const int js  = blockIdx.z;
    const int tid = threadIdx.x;       // 128

#pragma unroll
    for (int t = 0; t < 32; ++t) {
        int idx = tid + t * 128;       // 0..4095
        int c = idx >> 7;
        int j = idx & 127;
        int jj = js * 128 + j;
        float v = 0.f;
        if (c < 10)                       v = Wq[(k * 10 + c) * 512 + jj];
        else if (c < 20)                  v = Wk[(k * 10 + (c - 10)) * 512 + jj];
        else if (c < 30 && k == 0)        v = Wv[(c - 20) * 512 + jj];
        sS[c * 128 + j] = v;
    }
    __syncthreads();

    const int f  = fc * 32 + (tid & 31);
    const int cg = tid >> 5;           // 0..3, 8 cols each
    float acc[8];
#pragma unroll
    for (int i = 0; i < 8; ++i) acc[i] = 0.f;

    const float* wl = Wlin + ((size_t)k * HH + js * 128) * FF + f;
#pragma unroll 4
    for (int j = 0; j < 128; ++j) {
        float w = wl[(size_t)j * FF];  // coalesced across warp
#pragma unroll
        for (int i = 0; i < 8; ++i)
            acc[i] += w * sS[(cg * 8 + i) * 128 + j];   // broadcast LDS
    }
#pragma unroll
    for (int i = 0; i < 8; ++i)
        g_part[(((size_t)js * KK + k) * NC + cg * 8 + i) * FF + f] = acc[i];
}

// Kernel 1b: reduce 4 partials -> g_Wc. grid 512 x 256.
__global__ void reduce_wc() {
    int idx = blockIdx.x * 256 + threadIdx.x;   // < 131072
    const int S = KK * NC * FF;                 // 131072
    g_Wc[idx] = g_part[idx] + g_part[S + idx] + g_part[2 * S + idx] + g_part[3 * S + idx];
}

// ---------------------------------------------------------------------------
// Kernel 2: folded biases, one warp per (k,c). grid 16 x 256.
// ---------------------------------------------------------------------------
__global__ void precompute_bc(const float* __restrict__ blin,
                              const float* __restrict__ Wq, const float* __restrict__ bq,
                              const float* __restrict__ Wk, const float* __restrict__ bk,
                              const float* __restrict__ Wv, const float* __restrict__ bv) {
    int gw   = blockIdx.x * 8 + (threadIdx.x >> 5);   // 0..127
    int lane = threadIdx.x & 31;
    int k = gw >> 5;
    int c = gw & 31;
    const float* W = nullptr;
    float base = 0.f;
    if (c < 10)                { W = Wq + (k * 10 + c) * 512;        base = bq[k * 10 + c]; }
    else if (c < 20)           { W = Wk + (k * 10 + (c - 10)) * 512; base = bk[k * 10 + (c - 10)]; }
    else if (c < 30 && k == 0) { W = Wv + (c - 20) * 512;            base = bv[c - 20]; }
    float s = 0.f;
    if (W) {
        const float* bl = blin + k * 512;
#pragma unroll
        for (int t = 0; t < 16; ++t) s += bl[lane + 32 * t] * W[lane + 32 * t];
    }
#pragma unroll
    for (int o = 16; o; o >>= 1) s += __shfl_xor_sync(0xffffffffu, s, o);
    if (lane == 0) g_bc[gw] = W ? (base + s) : 0.f;
}

// ---------------------------------------------------------------------------
// Kernel 3: fused main. 256 blocks x 128 threads, 128 rows/block.
//  Phase 1: qkv GEMM with packed f32x2 FMAs (thread tile 8 rows x 4 cols)
//  Phase 2: per-row attention + softmax + logits + mean-softmax
// ---------------------------------------------------------------------------
#define SA_STRIDE 132   // sA[32][132]  (f-major, row contiguous; mult of 4)
#define SB_STRIDE 68    // sB[32][68]   (duplicated cols: [2c]=[2c+1]=B[c])
#define SQ_STRIDE 129   // sQ[128][129] (conflict-free row reads in phase 2)
#define SA_OFF 0
#define SB_OFF (32 * SA_STRIDE)
#define SQ_OFF (32 * SA_STRIDE + 32 * SB_STRIDE)
#define SMEM_FLOATS (SQ_OFF + 128 * SQ_STRIDE)

__global__ __launch_bounds__(128)
void fused_main(const float* __restrict__ w0, const float* __restrict__ w1,
                const float* __restrict__ w2, const float* __restrict__ w3,
                const float* __restrict__ Wfin, const float* __restrict__ bfin,
                float* __restrict__ out_outputs, float* __restrict__ out_attn) {
    extern __shared__ float sm[];
    float* sA = sm + SA_OFF;   // [f][row]
    float* sB = sm + SB_OFF;   // [f][2c dup]
    float* sQ = sm + SQ_OFF;   // [row][k*32+c]

    const int tid  = threadIdx.x;
    const int b0   = blockIdx.x * 128;
    const int cg   = tid >> 4;          // 0..7  (cols: warp3 -> cols 24..31)
    const int rg   = tid & 15;          // 0..15
    const int c0   = cg * 4;
    const int r0   = rg * 8;
    const int warp = tid >> 5;

    // ---------------- Phase 1: qkv GEMM, one k at a time ----------------
    for (int k = 0; k < KK; ++k) {
        const float* wk = (k == 0) ? w0 : (k == 1) ? w1 : (k == 2) ? w2 : w3;
        // for k>0 only cols 0..19 are consumed; warp 3 (cols 24..31) skips compute
        const bool active = (k == 0) || (warp < 3);

        unsigned long long accp[4][4];   // [row-pair][col], packed fp32x2
#pragma unroll
        for (int i = 0; i < 4; ++i)
#pragma unroll
            for (int j = 0; j < 4; ++j) accp[i][j] = 0ull;

        for (int ft = 0; ft < 32; ++ft) {
            const int fb = ft * 32;
            __syncthreads();   // previous tile fully consumed

            // A tile: 128 rows x 32 f -> sA[f][row]
#pragma unroll
            for (int t = 0; t < 8; ++t) {
                int idx = tid + t * 128;         // 0..1023
                int row = idx >> 3;
                int f4  = idx & 7;
                const float4 v = *(const float4*)(wk + (size_t)(b0 + row) * FF + fb + f4 * 4);
                sA[(f4 * 4 + 0) * SA_STRIDE + row] = v.x;
                sA[(f4 * 4 + 1) * SA_STRIDE + row] = v.y;
                sA[(f4 * 4 + 2) * SA_STRIDE + row] = v.z;
                sA[(f4 * 4 + 3) * SA_STRIDE + row] = v.w;
            }
            // B tile (duplicated): 32 cols x 32 f -> sB[f][2c],[2c+1]
#pragma unroll
            for (int t = 0; t < 8; ++t) {
                int idx = tid + t * 128;         // 0..1023
                int f = idx & 31;
                int c = idx >> 5;
                float v = g_Wc[((size_t)k * NC + c) * FF + fb + f];
                sB[f * SB_STRIDE + 2 * c]     = v;
                sB[f * SB_STRIDE + 2 * c + 1] = v;
            }
            __syncthreads();

            if (active) {
#pragma unroll
                for (int f = 0; f < 32; ++f) {
                    const unsigned long long* ap =
                        (const unsigned long long*)&sA[f * SA_STRIDE + r0];
                    const unsigned long long* bp =
                        (const unsigned long long*)&sB[f * SB_STRIDE + 2 * c0];
                    unsigned long long a0 = ap[0], a1 = ap[1], a2 = ap[2], a3 = ap[3];
                    unsigned long long bb0 = bp[0], bb1 = bp[1], bb2 = bp[2], bb3 = bp[3];
                    ffma2(accp[0][0], a0, bb0); ffma2(accp[0][1], a0, bb1);
                    ffma2(accp[0][2], a0, bb2); ffma2(accp[0][3], a0, bb3);
                    ffma2(accp[1][0], a1, bb0); ffma2(accp[1][1], a1, bb1);
                    ffma2(accp[1][2], a1, bb2); ffma2(accp[1][3], a1, bb3);
                    ffma2(accp[2][0], a2, bb0); ffma2(accp[2][1], a2, bb1);
                    ffma2(accp[2][2], a2, bb2); ffma2(accp[2][3], a2, bb3);
                    ffma2(accp[3][0], a3, bb0); ffma2(accp[3][1], a3, bb1);
                    ffma2(accp[3][2], a3, bb2); ffma2(accp[3][3], a3, bb3);
                }
            }
        }

        // bias + store to sQ (unpack)
        if (active) {
#pragma unroll
            for (int j = 0; j < 4; ++j) {
                const float bias = g_bc[k * NC + c0 + j];
#pragma unroll
                for (int ip = 0; ip < 4; ++ip) {
                    unsigned int lo = (unsigned int)(accp[ip][j] & 0xffffffffull);
                    unsigned int hi = (unsigned int)(accp[ip][j] >> 32);
                    sQ[(r0 + 2 * ip)     * SQ_STRIDE + k * NC + c0 + j] = __uint_as_float(lo) + bias;
                    sQ[(r0 + 2 * ip + 1) * SQ_STRIDE + k * NC + c0 + j] = __uint_as_float(hi) + bias;
                }
            }
        }
    }
    __syncthreads();

    // ---------------- Phase 2: per-row attention ----------------
    {
        const int r = tid;
        const int b = b0 + r;
        const float* qr = &sQ[r * SQ_STRIDE];

        float q[KK][EE];
#pragma unroll
        for (int k = 0; k < KK; ++k)
#pragma unroll
            for (int e = 0; e < EE; ++e) q[k][e] = qr[k * NC + e];

        float v0[EE];
#pragma unroll
        for (int m = 0; m < EE; ++m) v0[m] = qr[20 + m];

        float w0o[EE];
#pragma unroll
        for (int e = 0; e < EE; ++e) w0o[e] = 0.f;

        const float inv_sqrtE = 0.31622776601683794f;   // 1/sqrt(10)
        float* attn_row = out_attn + (size_t)b * (EE * EE);

#pragma unroll
        for (int l = 0; l < EE; ++l) {
            float kkv[KK];
#pragma unroll
            for (int k = 0; k < KK; ++k) kkv[k] = qr[k * NC + 10 + l];

            float col[EE];
#pragma unroll
            for (int e = 0; e < EE; ++e)
                col[e] = (q[0][e] * kkv[0] + q[1][e] * kkv[1] +
                          q[2][e] * kkv[2] + q[3][e] * kkv[3]) * inv_sqrtE;

            float mx = col[0];
#pragma unroll
            for (int e = 1; e < EE; ++e) mx = fmaxf(mx, col[e]);
            float p[EE], s = 0.f;
#pragma unroll
            for (int e = 0; e < EE; ++e) { p[e] = __expf(col[e] - mx); s += p[e]; }
            const float is = 1.f / s;
#pragma unroll
            for (int e = 0; e < EE; ++e) {
                p[e] *= is;
                attn_row[e * EE + l] = p[e];     // attn[b][e][l]
                w0o[e] += p[e] * v0[l];          // att_out[b,0,e]
            }
        }

        float oacc[CC];
#pragma unroll
        for (int c = 0; c < CC; ++c) oacc[c] = 0.f;

#pragma unroll
        for (int k = 0; k < KK; ++k) {
            float lg[CC];
#pragma unroll
            for (int c = 0; c < CC; ++c) {
                float s2 = bfin[k * CC + c];
#pragma unroll
                for (int e = 0; e < EE; ++e)
                    s2 += w0o[e] * Wfin[k * CC * EE + c * EE + e];
                lg[c] = s2;
            }
            float mx = lg[0];
#pragma unroll
            for (int c = 1; c < CC; ++c) mx = fmaxf(mx, lg[c]);
            float p[CC], s = 0.f;
#pragma unroll
            for (int c = 0; c < CC; ++c) { p[c] = __expf(lg[c] - mx); s += p[c]; }
            const float is = 1.f / s;
#pragma unroll
            for (int c = 0; c < CC; ++c) oacc[c] += p[c] * is;
        }

        float* outr = out_outputs + (size_t)b * CC;
#pragma unroll
        for (int c = 0; c < CC; ++c) outr[c] = oacc[c] * 0.25f;
    }
}

// ---------------------------------------------------------------------------
extern "C" void kernel_launch(void* const* d_in, const int* in_sizes, int n_in,
                              void* d_out, int out_size) {
    const float* w0   = (const float*)d_in[0];
    const float* w1   = (const float*)d_in[1];
    const float* w2   = (const float*)d_in[2];
    const float* w3   = (const float*)d_in[3];
    const float* Wlin = (const float*)d_in[4];
    const float* blin = (const float*)d_in[5];
    const float* Wq   = (const float*)d_in[6];
    const float* bq   = (const float*)d_in[7];
    const float* Wk   = (const float*)d_in[8];
    const float* bk   = (const float*)d_in[9];
    const float* Wv   = (const float*)d_in[10];
    const float* bv   = (const float*)d_in[11];
    const float* Wfin = (const float*)d_in[12];
    const float* bfin = (const float*)d_in[13];

    float* out      = (float*)d_out;
    float* out_attn = out + (size_t)BB * CC;   // outputs first, then attn

    const int smem_main = SMEM_FLOATS * 4;     // ~89.5 KB
    cudaFuncSetAttribute(fused_main, cudaFuncAttributeMaxDynamicSharedMemorySize, smem_main);

    precompute_part<<<dim3(4, 32, 4), 128>>>(Wlin, Wq, Wk, Wv);
    reduce_wc<<<512, 256>>>();
    precompute_bc<<<16, 256>>>(blin, Wq, bq, Wk, bk, Wv, bv);
    fused_main<<<BB / 128, 128, smem_main>>>(w0, w1, w2, w3, Wfin, bfin, out, out_attn);
}

// round 10
// speedup vs baseline: 3.6454x; 2.9521x over previous
#include <cuda_runtime.h>
#include <cuda_bf16.h>
#include <math.h>
#include <cstdint>

// Problem constants
#define BB   32768
#define FF   1024
#define HH   512
#define EE   10
#define CC   10
#define KK   4
#define NC   32       // cols per k in sQ: [0..9]=q, [10..19]=k, [20..29]=v(k==0)
#define KC   128      // K chunk
#define NKC  (FF/KC)  // 8

// B row stride in bf16 elems (272 bytes): conflict-free ldmatrix, 16B-aligned rows
#define BSTRIDE 136

// ---------------- device scratch (allocation-free) ----------------
__device__ float g_Wc[KK * NC * FF];            // folded fp32 weights [k][c][f]
__device__ float g_part[8 * KK * NC * FF];      // j-slice partials
__device__ float g_bc[KK * NC];                 // folded biases
// B tiles bf16 hi/lo, padded row-major image: [k][kc][split][32*BSTRIDE]
__device__ __align__(16) __nv_bfloat16 g_Wb[KK * NKC * 2 * 32 * BSTRIDE];

// ---------------- PTX helpers ----------------
__device__ __forceinline__ uint32_t smem_u32(const void* p) {
    uint32_t a;
    asm("{ .reg .u64 t; cvta.to.shared.u64 t, %1; cvt.u32.u64 %0, t; }" : "=r"(a) : "l"(p));
    return a;
}
__device__ __forceinline__ void ldsm4(uint32_t* r, uint32_t addr) {
    asm volatile("ldmatrix.sync.aligned.m8n8.x4.shared.b16 {%0,%1,%2,%3}, [%4];"
        : "=r"(r[0]), "=r"(r[1]), "=r"(r[2]), "=r"(r[3]) : "r"(addr));
}
__device__ __forceinline__ void mma_bf16(float* d, const uint32_t* a, const uint32_t* b) {
    asm volatile("mma.sync.aligned.m16n8k16.row.col.f32.bf16.bf16.f32 "
        "{%0,%1,%2,%3}, {%4,%5,%6,%7}, {%8,%9}, {%0,%1,%2,%3};"
        : "+f"(d[0]), "+f"(d[1]), "+f"(d[2]), "+f"(d[3])
        : "r"(a[0]), "r"(a[1]), "r"(a[2]), "r"(a[3]), "r"(b[0]), "r"(b[1]));
}
#define CVT_BF16X2(res, a, b) \
    asm("cvt.rn.satfinite.bf16x2.f32 %0, %1, %2;" : "=r"(res) : "f"(b), "f"(a))

// ---------------------------------------------------------------------------
// Kernel 1a: partial fold over 8 j-slices of 64.
// grid (4 k, 32 fchunk, 8 jslice) x 128 threads
// ---------------------------------------------------------------------------
__global__ void precompute_part(const float* __restrict__ Wlin,
                                const float* __restrict__ Wq,
                                const float* __restrict__ Wk,
                                const float* __restrict__ Wv) {
    __shared__ float sS[32 * 64];
    const int k = blockIdx.x, fc = blockIdx.y, js = blockIdx.z;
    const int tid = threadIdx.x;

#pragma unroll
    for (int t = 0; t < 16; ++t) {
        int idx = tid + t * 128;       // 0..2047
        int c = idx >> 6;
        int j = idx & 63;
        int jj = js * 64 + j;
        float v = 0.f;
        if (c < 10)                v = Wq[(k * 10 + c) * 512 + jj];
        else if (c < 20)           v = Wk[(k * 10 + (c - 10)) * 512 + jj];
        else if (c < 30 && k == 0) v = Wv[(c - 20) * 512 + jj];
        sS[c * 64 + j] = v;
    }
    __syncthreads();

    const int f  = fc * 32 + (tid & 31);
    const int cg = tid >> 5;
    float acc[8];
#pragma unroll
    for (int i = 0; i < 8; ++i) acc[i] = 0.f;
    const float* wl = Wlin + ((size_t)k * HH + js * 64) * FF + f;
#pragma unroll 4
    for (int j = 0; j < 64; ++j) {
        float w = wl[(size_t)j * FF];
#pragma unroll
        for (int i = 0; i < 8; ++i)
            acc[i] += w * sS[(cg * 8 + i) * 64 + j];
    }
#pragma unroll
    for (int i = 0; i < 8; ++i)
        g_part[(((size_t)js * KK + k) * NC + cg * 8 + i) * FF + f] = acc[i];
}

__global__ void reduce_wc() {
    int idx = blockIdx.x * 256 + threadIdx.x;   // < 131072
    const int S = KK * NC * FF;
    float s = 0.f;
#pragma unroll
    for (int js = 0; js < 8; ++js) s += g_part[(size_t)js * S + idx];
    g_Wc[idx] = s;
}

// ---------------------------------------------------------------------------
// Kernel 1c: bake B tiles (bf16 hi/lo) as padded row-major images.
// grid (4 k, 8 kc) x 128
// ---------------------------------------------------------------------------
__global__ void make_wb() {
    const int k = blockIdx.x, kc = blockIdx.y, tid = threadIdx.x;
    __nv_bfloat16* hi = g_Wb + (((size_t)(k * NKC + kc)) * 2 + 0) * 32 * BSTRIDE;
    __nv_bfloat16* lo = g_Wb + (((size_t)(k * NKC + kc)) * 2 + 1) * 32 * BSTRIDE;
#pragma unroll
    for (int t = 0; t < 32; ++t) {
        int idx = tid + t * 128;       // 0..4095
        int c = idx >> 7;              // 0..31
        int f = idx & 127;
        float w = g_Wc[((size_t)k * NC + c) * FF + kc * KC + f];
        __nv_bfloat16 h = __float2bfloat16(w);
        __nv_bfloat16 l = __float2bfloat16(w - __bfloat162float(h));
        hi[c * BSTRIDE + f] = h;
        lo[c * BSTRIDE + f] = l;
    }
    // zero the pad columns so copies carry no NaN garbage (harmless but clean)
    if (tid < 32) {
#pragma unroll
        for (int f = 128; f < BSTRIDE; ++f) {
            hi[tid * BSTRIDE + f] = __float2bfloat16(0.f);
            lo[tid * BSTRIDE + f] = __float2bfloat16(0.f);
        }
    }
}

// ---------------------------------------------------------------------------
// Kernel 2: folded biases, one warp per (k,c).
// ---------------------------------------------------------------------------
__global__ void precompute_bc(const float* __restrict__ blin,
                              const float* __restrict__ Wq, const float* __restrict__ bq,
                              const float* __restrict__ Wk, const float* __restrict__ bk,
                              const float* __restrict__ Wv, const float* __restrict__ bv) {
    int gw   = blockIdx.x * 8 + (threadIdx.x >> 5);
    int lane = threadIdx.x & 31;
    int k = gw >> 5, c = gw & 31;
    const float* W = nullptr;
    float base = 0.f;
    if (c < 10)                { W = Wq + (k * 10 + c) * 512;        base = bq[k * 10 + c]; }
    else if (c < 20)           { W = Wk + (k * 10 + (c - 10)) * 512; base = bk[k * 10 + (c - 10)]; }
    else if (c < 30 && k == 0) { W = Wv + (c - 20) * 512;            base = bv[c - 20]; }
    float s = 0.f;
    if (W) {
        const float* bl = blin + k * 512;
#pragma unroll
        for (int t = 0; t < 16; ++t) s += bl[lane + 32 * t] * W[lane + 32 * t];
    }
#pragma unroll
    for (int o = 16; o; o >>= 1) s += __shfl_xor_sync(0xffffffffu, s, o);
    if (lane == 0) g_bc[gw] = W ? (base + s) : 0.f;
}

// ---------------------------------------------------------------------------
// Kernel 3: fused HMMA GEMM + attention.
// 256 blocks x 256 threads (8 warps), 128 rows/block.
// SMEM (bytes):
//   [0..512)        bias (128 floats)
//   [1024..35840)   A hi  (128 x 136 bf16)
//   [35840..70656)  A lo
//   [70656..79360)  B hi  (32 x 136 bf16)
//   [79360..88064)  B lo
//   sQ (epilogue) reuses [1024..68608): 128 rows x 132 floats
// ---------------------------------------------------------------------------
#define S_BC   0
#define S_AHI  1024
#define S_ALO  35840
#define S_BHI  70656
#define S_BLO  79360
#define SMEM_BYTES 88064
#define SQ_STRIDE 132

__global__ __launch_bounds__(256, 2)
void fused_main(const float* __restrict__ w0, const float* __restrict__ w1,
                const float* __restrict__ w2, const float* __restrict__ w3,
                const float* __restrict__ Wfin, const float* __restrict__ bfin,
                float* __restrict__ out_outputs, float* __restrict__ out_attn) {
    extern __shared__ char smem[];
    const uint32_t sb = smem_u32(smem);
    const int tid  = threadIdx.x;
    const int wid  = tid >> 5;
    const int lane = tid & 31;
    const int b0   = blockIdx.x * 128;

    if (tid < 128) ((float*)(smem + S_BC))[tid] = g_bc[tid];

    // ldmatrix addresses (per-thread constants, +s*32 per k-step)
    const uint32_t aRowOff = (uint32_t)((wid * 16 + (lane & 7) + ((lane >> 3) & 1) * 8) * (BSTRIDE * 2)
                                        + (lane >> 4) * 16);
    const uint32_t aHiBase = sb + S_AHI + aRowOff;
    const uint32_t aLoBase = sb + S_ALO + aRowOff;
    const uint32_t bRow0   = (uint32_t)((((lane >> 4) & 1) * 8 + (lane & 7)) * (BSTRIDE * 2)
                                        + ((lane >> 3) & 1) * 16);
    const uint32_t bHi0 = sb + S_BHI + bRow0;                      // n-tiles 0,1
    const uint32_t bHi1 = sb + S_BHI + bRow0 + 16 * (BSTRIDE * 2); // n-tiles 2,3
    const uint32_t bLo0 = sb + S_BLO + bRow0;
    const uint32_t bLo1 = sb + S_BLO + bRow0 + 16 * (BSTRIDE * 2);

    float acc[KK][4][4];   // [k][n-tile][frag]; k>=1,nt==3 never touched -> dead
#pragma unroll
    for (int k = 0; k < KK; ++k)
#pragma unroll
        for (int nt = 0; nt < 4; ++nt)
#pragma unroll
            for (int i = 0; i < 4; ++i) acc[k][nt][i] = 0.f;

#pragma unroll
    for (int k = 0; k < KK; ++k) {
        const float* wk = (k == 0) ? w0 : (k == 1) ? w1 : (k == 2) ? w2 : w3;
        for (int kc = 0; kc < NKC; ++kc) {
            // ---- global loads: A batch0 (8 float4/thread) + B image (uint4) ----
            float4 va[8];
#pragma unroll
            for (int u = 0; u < 8; ++u) {
                int idx = tid + u * 256;            // 0..2047
                int row = idx >> 5, f4 = idx & 31;
                va[u] = *(const float4*)(wk + (size_t)(b0 + row) * FF + kc * KC + f4 * 4);
            }
            const uint4* srcB = (const uint4*)(g_Wb + ((size_t)(k * NKC + kc)) * 2 * 32 * BSTRIDE);
            uint4 vb[5];
#pragma unroll
            for (int u = 0; u < 4; ++u) vb[u] = srcB[tid + u * 256];
            if (tid < 64) vb[4] = srcB[tid + 1024];   // 1088 uint4 total

            // ---- store B ----
            uint4* dstB = (uint4*)(smem + S_BHI);
#pragma unroll
            for (int u = 0; u < 4; ++u) dstB[tid + u * 256] = vb[u];
            if (tid < 64) dstB[tid + 1024] = vb[4];

            // ---- convert A batch0 -> hi/lo STS; then batch1 ----
#pragma unroll
            for (int g = 0; g < 2; ++g) {
                float4 vn[8];
                if (g == 0) {
#pragma unroll
                    for (int u = 0; u < 8; ++u) {
                        int idx = tid + u * 256 + 2048;
                        int row = idx >> 5, f4 = idx & 31;
                        vn[u] = *(const float4*)(wk + (size_t)(b0 + row) * FF + kc * KC + f4 * 4);
                    }
                }
#pragma unroll
                for (int u = 0; u < 8; ++u) {
                    int idx = tid + u * 256 + g * 2048;
                    int row = idx >> 5, f4 = idx & 31;
                    int off = row * (BSTRIDE * 2) + f4 * 8;
                    float4 v = va[u];
                    uint32_t hp0, hp1, lp0, lp1;
                    CVT_BF16X2(hp0, v.x, v.y);
                    CVT_BF16X2(hp1, v.z, v.w);
                    float h0 = __uint_as_float(hp0 << 16);
                    float h1 = __uint_as_float(hp0 & 0xffff0000u);
                    float h2 = __uint_as_float(hp1 << 16);
                    float h3 = __uint_as_float(hp1 & 0xffff0000u);
                    CVT_BF16X2(lp0, v.x - h0, v.y - h1);
                    CVT_BF16X2(lp1, v.z - h2, v.w - h3);
                    *(uint2*)(smem + S_AHI + off) = make_uint2(hp0, hp1);
                    *(uint2*)(smem + S_ALO + off) = make_uint2(lp0, lp1);
                }
                if (g == 0) {
#pragma unroll
                    for (int u = 0; u < 8; ++u) va[u] = vn[u];
                }
            }
            __syncthreads();

            // ---- 8 k-steps of ldmatrix + HMMA ----
#pragma unroll
            for (int s = 0; s < 8; ++s) {
                const uint32_t so = (uint32_t)(s * 32);
                uint32_t ah[4], al[4], bh0[4], bh1[4], bl0[4], bl1[4];
                ldsm4(ah,  aHiBase + so);
                ldsm4(al,  aLoBase + so);
                ldsm4(bh0, bHi0 + so);
                ldsm4(bh1, bHi1 + so);
                ldsm4(bl0, bLo0 + so);
                ldsm4(bl1, bLo1 + so);
                // nt0
                mma_bf16(acc[k][0], ah, bh0 + 0);
                mma_bf16(acc[k][0], ah, bl0 + 0);
                mma_bf16(acc[k][0], al, bh0 + 0);
                // nt1
                mma_bf16(acc[k][1], ah, bh0 + 2);
                mma_bf16(acc[k][1], ah, bl0 + 2);
                mma_bf16(acc[k][1], al, bh0 + 2);
                // nt2
                mma_bf16(acc[k][2], ah, bh1 + 0);
                mma_bf16(acc[k][2], ah, bl1 + 0);
                mma_bf16(acc[k][2], al, bh1 + 0);
                // nt3 only needed for k == 0 (v columns)
                if (k == 0) {
                    mma_bf16(acc[k][3], ah, bh1 + 2);
                    mma_bf16(acc[k][3], ah, bl1 + 2);
                    mma_bf16(acc[k][3], al, bh1 + 2);
                }
            }
            __syncthreads();
        }
    }

    // ---- dump D fragments to sQ (reuses A region) ----
    float* sQ = (float*)(smem + S_AHI);
    {
        const int r0 = wid * 16 + (lane >> 2);
        const int cb = (lane & 3) * 2;
#pragma unroll
        for (int k = 0; k < KK; ++k) {
#pragma unroll
            for (int nt = 0; nt < 4; ++nt) {
                if (k > 0 && nt == 3) continue;
                int c = k * NC + nt * 8 + cb;
                *(float2*)&sQ[r0 * SQ_STRIDE + c]       = make_float2(acc[k][nt][0], acc[k][nt][1]);
                *(float2*)&sQ[(r0 + 8) * SQ_STRIDE + c] = make_float2(acc[k][nt][2], acc[k][nt][3]);
            }
        }
    }
    __syncthreads();

    // ---- phase 2: per-row attention (threads 0..127) ----
    if (tid < 128) {
        const int b = b0 + tid;
        const float* qr  = &sQ[tid * SQ_STRIDE];
        const float* sBC = (const float*)(smem + S_BC);

        float q[KK][EE], ke[KK][EE], v0[EE];
#pragma unroll
        for (int k = 0; k < KK; ++k)
#pragma unroll
            for (int e = 0; e < EE; ++e) {
                q[k][e]  = qr[k * NC + e]      + sBC[k * NC + e];
                ke[k][e] = qr[k * NC + 10 + e] + sBC[k * NC + 10 + e];
            }
#pragma unroll
        for (int e = 0; e < EE; ++e) v0[e] = qr[20 + e] + sBC[20 + e];

        float w0o[EE];
#pragma unroll
        for (int e = 0; e < EE; ++e) w0o[e] = 0.f;
        const float inv_sqrtE = 0.31622776601683794f;   // 1/sqrt(10)
        float* attn_row = out_attn + (size_t)b * (EE * EE);

#pragma unroll
        for (int l = 0; l < EE; ++l) {
            float col[EE];
#pragma unroll
            for (int e = 0; e < EE; ++e)
                col[e] = (q[0][e] * ke[0][l] + q[1][e] * ke[1][l] +
                          q[2][e] * ke[2][l] + q[3][e] * ke[3][l]) * inv_sqrtE;
            float mx = col[0];
#pragma unroll
            for (int e = 1; e < EE; ++e) mx = fmaxf(mx, col[e]);
            float p[EE], s = 0.f;
#pragma unroll
            for (int e = 0; e < EE; ++e) { p[e] = __expf(col[e] - mx); s += p[e]; }
            const float is = 1.f / s;
#pragma unroll
            for (int e = 0; e < EE; ++e) {
                p[e] *= is;
                attn_row[e * EE + l] = p[e];
                w0o[e] += p[e] * v0[l];
            }
        }

        float oacc[CC];
#pragma unroll
        for (int c = 0; c < CC; ++c) oacc[c] = 0.f;
#pragma unroll
        for (int k = 0; k < KK; ++k) {
            float lg[CC];
#pragma unroll
            for (int c = 0; c < CC; ++c) {
                float s2 = bfin[k * CC + c];
#pragma unroll
                for (int e = 0; e < EE; ++e)
                    s2 += w0o[e] * Wfin[k * CC * EE + c * EE + e];
                lg[c] = s2;
            }
            float mx = lg[0];
#pragma unroll
            for (int c = 1; c < CC; ++c) mx = fmaxf(mx, lg[c]);
            float p[CC], s = 0.f;
#pragma unroll
            for (int c = 0; c < CC; ++c) { p[c] = __expf(lg[c] - mx); s += p[c]; }
            const float is = 1.f / s;
#pragma unroll
            for (int c = 0; c < CC; ++c) oacc[c] += p[c] * is;
        }
        float* outr = out_outputs + (size_t)b * CC;
#pragma unroll
        for (int c = 0; c < CC; ++c) outr[c] = oacc[c] * 0.25f;
    }
}

// ---------------------------------------------------------------------------
extern "C" void kernel_launch(void* const* d_in, const int* in_sizes, int n_in,
                              void* d_out, int out_size) {
    const float* w0   = (const float*)d_in[0];
    const float* w1   = (const float*)d_in[1];
    const float* w2   = (const float*)d_in[2];
    const float* w3   = (const float*)d_in[3];
    const float* Wlin = (const float*)d_in[4];
    const float* blin = (const float*)d_in[5];
    const float* Wq   = (const float*)d_in[6];
    const float* bq   = (const float*)d_in[7];
    const float* Wk   = (const float*)d_in[8];
    const float* bk   = (const float*)d_in[9];
    const float* Wv   = (const float*)d_in[10];
    const float* bv   = (const float*)d_in[11];
    const float* Wfin = (const float*)d_in[12];
    const float* bfin = (const float*)d_in[13];

    float* out      = (float*)d_out;
    float* out_attn = out + (size_t)BB * CC;

    cudaFuncSetAttribute(fused_main, cudaFuncAttributeMaxDynamicSharedMemorySize, SMEM_BYTES);

    precompute_part<<<dim3(4, 32, 8), 128>>>(Wlin, Wq, Wk, Wv);
    reduce_wc<<<512, 256>>>();
    make_wb<<<dim3(4, 8), 128>>>();
    precompute_bc<<<16, 256>>>(blin, Wq, bq, Wk, bk, Wv, bv);
    fused_main<<<BB / 128, 256, SMEM_BYTES>>>(w0, w1, w2, w3, Wfin, bfin, out, out_attn);
}

// round 11
// speedup vs baseline: 3.9030x; 1.0707x over previous
#include <cuda_runtime.h>
#include <cuda_bf16.h>
#include <math.h>
#include <cstdint>

// Problem constants
#define BB   32768
#define FF   1024
#define HH   512
#define EE   10
#define CC   10
#define KK   4
#define NC   32       // cols per k: [0..9]=q, [10..19]=k, [20..29]=v(k==0)
#define KC   128      // K chunk
#define NKC  (FF/KC)  // 8

// B row stride in bf16 elems (272 bytes): conflict-free ldmatrix, 16B-aligned rows
#define BSTRIDE 136

// ---------------- device scratch (allocation-free) ----------------
__device__ float g_part[8 * KK * NC * FF];      // j-slice partials
__device__ float g_bc[KK * NC];                 // folded biases
// B tiles bf16 hi/lo, padded row-major image: [k][kc][split][32*BSTRIDE]
// (pad columns 128..135 are never written -> stay zero from module load)
__device__ __align__(16) __nv_bfloat16 g_Wb[KK * NKC * 2 * 32 * BSTRIDE];
// qkv staging: [b][k*32+c]  (16 MB)
__device__ __align__(16) float g_qkv[(size_t)BB * 128];

// ---------------- PTX helpers ----------------
__device__ __forceinline__ uint32_t smem_u32(const void* p) {
    uint32_t a;
    asm("{ .reg .u64 t; cvta.to.shared.u64 t, %1; cvt.u32.u64 %0, t; }" : "=r"(a) : "l"(p));
    return a;
}
__device__ __forceinline__ void ldsm4(uint32_t* r, uint32_t addr) {
    asm volatile("ldmatrix.sync.aligned.m8n8.x4.shared.b16 {%0,%1,%2,%3}, [%4];"
        : "=r"(r[0]), "=r"(r[1]), "=r"(r[2]), "=r"(r[3]) : "r"(addr));
}
__device__ __forceinline__ void mma_bf16(float* d, const uint32_t* a, const uint32_t* b) {
    asm volatile("mma.sync.aligned.m16n8k16.row.col.f32.bf16.bf16.f32 "
        "{%0,%1,%2,%3}, {%4,%5,%6,%7}, {%8,%9}, {%0,%1,%2,%3};"
        : "+f"(d[0]), "+f"(d[1]), "+f"(d[2]), "+f"(d[3])
        : "r"(a[0]), "r"(a[1]), "r"(a[2]), "r"(a[3]), "r"(b[0]), "r"(b[1]));
}
#define CVT_BF16X2(res, a, b) \
    asm("cvt.rn.satfinite.bf16x2.f32 %0, %1, %2;" : "=r"(res) : "f"(b), "f"(a))

// ---------------------------------------------------------------------------
// Kernel 1: partial fold over 8 j-slices of 64.
// grid (4 k, 32 fchunk, 8 jslice) x 128 threads
// ---------------------------------------------------------------------------
__global__ void precompute_part(const float* __restrict__ Wlin,
                                const float* __restrict__ Wq,
                                const float* __restrict__ Wk,
                                const float* __restrict__ Wv) {
    __shared__ float sS[32 * 64];
    const int k = blockIdx.x, fc = blockIdx.y, js = blockIdx.z;
    const int tid = threadIdx.x;

#pragma unroll
    for (int t = 0; t < 16; ++t) {
        int idx = tid + t * 128;       // 0..2047
        int c = idx >> 6;
        int j = idx & 63;
        int jj = js * 64 + j;
        float v = 0.f;
        if (c < 10)                v = Wq[(k * 10 + c) * 512 + jj];
        else if (c < 20)           v = Wk[(k * 10 + (c - 10)) * 512 + jj];
        else if (c < 30 && k == 0) v = Wv[(c - 20) * 512 + jj];
        sS[c * 64 + j] = v;
    }
    __syncthreads();

    const int f  = fc * 32 + (tid & 31);
    const int cg = tid >> 5;
    float acc[8];
#pragma unroll
    for (int i = 0; i < 8; ++i) acc[i] = 0.f;
    const float* wl = Wlin + ((size_t)k * HH + js * 64) * FF + f;
#pragma unroll 4
    for (int j = 0; j < 64; ++j) {
        float w = wl[(size_t)j * FF];
#pragma unroll
        for (int i = 0; i < 8; ++i)
            acc[i] += w * sS[(cg * 8 + i) * 64 + j];
    }
#pragma unroll
    for (int i = 0; i < 8; ++i)
        g_part[(((size_t)js * KK + k) * NC + cg * 8 + i) * FF + f] = acc[i];
}

// ---------------------------------------------------------------------------
// Kernel 2 (fused finalize): blocks 0..511 reduce partials -> bf16 hi/lo B
// images directly; blocks 512..527 compute folded biases (one warp per (k,c)).
// ---------------------------------------------------------------------------
__global__ void finalize(const float* __restrict__ blin,
                         const float* __restrict__ Wq, const float* __restrict__ bq,
                         const float* __restrict__ Wk, const float* __restrict__ bk,
                         const float* __restrict__ Wv, const float* __restrict__ bv) {
    const int blk = blockIdx.x;
    if (blk < 512) {
        int idx = blk * 256 + threadIdx.x;     // < 131072
        const int S = KK * NC * FF;
        float s = 0.f;
#pragma unroll
        for (int js = 0; js < 8; ++js) s += g_part[(size_t)js * S + idx];
        int k  = idx >> 15;          // / (NC*FF)
        int c  = (idx >> 10) & 31;
        int f  = idx & 1023;
        int kc = f >> 7;
        int fl = f & 127;
        __nv_bfloat16 h = __float2bfloat16(s);
        __nv_bfloat16 l = __float2bfloat16(s - __bfloat162float(h));
        size_t base = ((size_t)(k * NKC + kc) * 2) * 32 * BSTRIDE;
        g_Wb[base + c * BSTRIDE + fl]                 = h;
        g_Wb[base + 32 * BSTRIDE + c * BSTRIDE + fl]  = l;
    } else {
        int gw   = (blk - 512) * 8 + (threadIdx.x >> 5);   // 0..127
        int lane = threadIdx.x & 31;
        int k = gw >> 5, c = gw & 31;
        const float* W = nullptr;
        float base = 0.f;
        if (c < 10)                { W = Wq + (k * 10 + c) * 512;        base = bq[k * 10 + c]; }
        else if (c < 20)           { W = Wk + (k * 10 + (c - 10)) * 512; base = bk[k * 10 + (c - 10)]; }
        else if (c < 30 && k == 0) { W = Wv + (c - 20) * 512;            base = bv[c - 20]; }
        float s = 0.f;
        if (W) {
            const float* bl = blin + k * 512;
#pragma unroll
            for (int t = 0; t < 16; ++t) s += bl[lane + 32 * t] * W[lane + 32 * t];
        }
#pragma unroll
        for (int o = 16; o; o >>= 1) s += __shfl_xor_sync(0xffffffffu, s, o);
        if (lane == 0) g_bc[gw] = W ? (base + s) : 0.f;
    }
}

// ---------------------------------------------------------------------------
// Kernel 3: fused HMMA GEMM + attention.
// 256 blocks x 256 threads (8 warps), 128 rows/block.
// Warps 0..3 each own 32 rows (2 m16 tiles) for MMA; all 8 warps load/convert.
// Per-k accumulators are dumped to g_qkv (L2-hot), freeing registers.
// SMEM (bytes):
//   [0..512)        bias (128 floats)
//   [1024..35840)   A hi  (128 x 136 bf16)
//   [35840..70656)  A lo
//   [70656..79360)  B hi  (32 x 136 bf16)
//   [79360..88064)  B lo
// ---------------------------------------------------------------------------
#define S_BC   0
#define S_AHI  1024
#define S_ALO  35840
#define S_BHI  70656
#define S_BLO  79360
#define SMEM_BYTES 88064

__global__ __launch_bounds__(256, 2)
void fused_main(const float* __restrict__ w0, const float* __restrict__ w1,
                const float* __restrict__ w2, const float* __restrict__ w3,
                const float* __restrict__ Wfin, const float* __restrict__ bfin,
                float* __restrict__ out_outputs, float* __restrict__ out_attn) {
    extern __shared__ char smem[];
    const uint32_t sb = smem_u32(smem);
    const int tid  = threadIdx.x;
    const int wid  = tid >> 5;
    const int lane = tid & 31;
    const int b0   = blockIdx.x * 128;

    if (tid < 128) ((float*)(smem + S_BC))[tid] = g_bc[tid];

    // ldmatrix addresses for MMA warps (wid < 4): rows wid*32 .. wid*32+31
    const uint32_t aRowOff = (uint32_t)((wid * 32 + (lane & 7) + ((lane >> 3) & 1) * 8) * (BSTRIDE * 2)
                                        + (lane >> 4) * 16);
    const uint32_t aHi0 = sb + S_AHI + aRowOff;
    const uint32_t aHi1 = aHi0 + 16 * (BSTRIDE * 2);
    const uint32_t aLo0 = sb + S_ALO + aRowOff;
    const uint32_t aLo1 = aLo0 + 16 * (BSTRIDE * 2);
    const uint32_t bRow0 = (uint32_t)((((lane >> 4) & 1) * 8 + (lane & 7)) * (BSTRIDE * 2)
                                      + ((lane >> 3) & 1) * 16);
    const uint32_t bHi0 = sb + S_BHI + bRow0;                      // n-tiles 0,1
    const uint32_t bHi1 = sb + S_BHI + bRow0 + 16 * (BSTRIDE * 2); // n-tiles 2,3
    const uint32_t bLo0 = sb + S_BLO + bRow0;
    const uint32_t bLo1 = sb + S_BLO + bRow0 + 16 * (BSTRIDE * 2);

#pragma unroll
    for (int k = 0; k < KK; ++k) {
        const float* wk = (k == 0) ? w0 : (k == 1) ? w1 : (k == 2) ? w2 : w3;

        float acc[2][4][4];   // [m-tile][n-tile][frag]; k>0,nt3 dead
#pragma unroll
        for (int mt = 0; mt < 2; ++mt)
#pragma unroll
            for (int nt = 0; nt < 4; ++nt)
#pragma unroll
                for (int i = 0; i < 4; ++i) acc[mt][nt][i] = 0.f;

        for (int kc = 0; kc < NKC; ++kc) {
            // ---- global loads: A batch0 (8 float4/thread) + B image (uint4) ----
            float4 va[8];
#pragma unroll
            for (int u = 0; u < 8; ++u) {
                int idx = tid + u * 256;            // 0..2047
                int row = idx >> 5, f4 = idx & 31;
                va[u] = *(const float4*)(wk + (size_t)(b0 + row) * FF + kc * KC + f4 * 4);
            }
            const uint4* srcB = (const uint4*)(g_Wb + ((size_t)(k * NKC + kc)) * 2 * 32 * BSTRIDE);
            uint4 vb[5];
#pragma unroll
            for (int u = 0; u < 4; ++u) vb[u] = srcB[tid + u * 256];
            if (tid < 64) vb[4] = srcB[tid + 1024];   // 1088 uint4 total

            // ---- store B ----
            uint4* dstB = (uint4*)(smem + S_BHI);
#pragma unroll
            for (int u = 0; u < 4; ++u) dstB[tid + u * 256] = vb[u];
            if (tid < 64) dstB[tid + 1024] = vb[4];

            // ---- convert A batch0 -> hi/lo STS; then batch1 ----
#pragma unroll
            for (int g = 0; g < 2; ++g) {
                float4 vn[8];
                if (g == 0) {
#pragma unroll
                    for (int u = 0; u < 8; ++u) {
                        int idx = tid + u * 256 + 2048;
                        int row = idx >> 5, f4 = idx & 31;
                        vn[u] = *(const float4*)(wk + (size_t)(b0 + row) * FF + kc * KC + f4 * 4);
                    }
                }
#pragma unroll
                for (int u = 0; u < 8; ++u) {
                    int idx = tid + u * 256 + g * 2048;
                    int row = idx >> 5, f4 = idx & 31;
                    int off = row * (BSTRIDE * 2) + f4 * 8;
                    float4 v = va[u];
                    uint32_t hp0, hp1, lp0, lp1;
                    CVT_BF16X2(hp0, v.x, v.y);
                    CVT_BF16X2(hp1, v.z, v.w);
                    float h0 = __uint_as_float(hp0 << 16);
                    float h1 = __uint_as_float(hp0 & 0xffff0000u);
                    float h2 = __uint_as_float(hp1 << 16);
                    float h3 = __uint_as_float(hp1 & 0xffff0000u);
                    CVT_BF16X2(lp0, v.x - h0, v.y - h1);
                    CVT_BF16X2(lp1, v.z - h2, v.w - h3);
                    *(uint2*)(smem + S_AHI + off) = make_uint2(hp0, hp1);
                    *(uint2*)(smem + S_ALO + off) = make_uint2(lp0, lp1);
                }
                if (g == 0) {
#pragma unroll
                    for (int u = 0; u < 8; ++u) va[u] = vn[u];
                }
            }
            __syncthreads();

            // ---- 8 k-steps of ldmatrix + HMMA (warps 0..3 only) ----
            if (wid < 4) {
#pragma unroll
                for (int s = 0; s < 8; ++s) {
                    const uint32_t so = (uint32_t)(s * 32);
                    uint32_t ah0[4], ah1[4], al0[4], al1[4];
                    uint32_t bh0[4], bh1[4], bl0[4], bl1[4];
                    ldsm4(ah0, aHi0 + so);
                    ldsm4(al0, aLo0 + so);
                    ldsm4(ah1, aHi1 + so);
                    ldsm4(al1, aLo1 + so);
                    ldsm4(bh0, bHi0 + so);
                    ldsm4(bh1, bHi1 + so);
                    ldsm4(bl0, bLo0 + so);
                    ldsm4(bl1, bLo1 + so);
                    // m-tile 0
                    mma_bf16(acc[0][0], ah0, bh0 + 0);
                    mma_bf16(acc[0][0], ah0, bl0 + 0);
                    mma_bf16(acc[0][0], al0, bh0 + 0);
                    mma_bf16(acc[0][1], ah0, bh0 + 2);
                    mma_bf16(acc[0][1], ah0, bl0 + 2);
                    mma_bf16(acc[0][1], al0, bh0 + 2);
                    mma_bf16(acc[0][2], ah0, bh1 + 0);
                    mma_bf16(acc[0][2], ah0, bl1 + 0);
                    mma_bf16(acc[0][2], al0, bh1 + 0);
                    if (k == 0) {
                        mma_bf16(acc[0][3], ah0, bh1 + 2);
                        mma_bf16(acc[0][3], ah0, bl1 + 2);
                        mma_bf16(acc[0][3], al0, bh1 + 2);
                    }
                    // m-tile 1
                    mma_bf16(acc[1][0], ah1, bh0 + 0);
                    mma_bf16(acc[1][0], ah1, bl0 + 0);
                    mma_bf16(acc[1][0], al1, bh0 + 0);
                    mma_bf16(acc[1][1], ah1, bh0 + 2);
                    mma_bf16(acc[1][1], ah1, bl0 + 2);
                    mma_bf16(acc[1][1], al1, bh0 + 2);
                    mma_bf16(acc[1][2], ah1, bh1 + 0);
                    mma_bf16(acc[1][2], ah1, bl1 + 0);
                    mma_bf16(acc[1][2], al1, bh1 + 0);
                    if (k == 0) {
                        mma_bf16(acc[1][3], ah1, bh1 + 2);
                        mma_bf16(acc[1][3], ah1, bl1 + 2);
                        mma_bf16(acc[1][3], al1, bh1 + 2);
                    }
                }
            }
            __syncthreads();
        }

        // ---- dump this k's accumulators to g_qkv (L2-hot) ----
        if (wid < 4) {
            const int rr = wid * 32 + (lane >> 2);
            const int cb = (lane & 3) * 2;
#pragma unroll
            for (int mt = 0; mt < 2; ++mt) {
#pragma unroll
                for (int nt = 0; nt < 4; ++nt) {
                    if (k > 0 && nt == 3) continue;
                    int c = k * NC + nt * 8 + cb;
                    int r = rr + mt * 16;
                    *(float2*)&g_qkv[(size_t)(b0 + r) * 128 + c] =
                        make_float2(acc[mt][nt][0], acc[mt][nt][1]);
                    *(float2*)&g_qkv[(size_t)(b0 + r + 8) * 128 + c] =
                        make_float2(acc[mt][nt][2], acc[mt][nt][3]);
                }
            }
        }
    }
    __syncthreads();   // g_qkv writes visible block-wide

    // ---- phase 2: per-row attention (threads 0..127) ----
    if (tid < 128) {
        const int b = b0 + tid;
        const float* sBC = (const float*)(smem + S_BC);
        const float4* qr4 = (const float4*)(g_qkv + (size_t)b * 128);

        float qv[KK][32];
#pragma unroll
        for (int k = 0; k < KK; ++k) {
#pragma unroll
            for (int t = 0; t < 8; ++t) {
                float4 v = qr4[k * 8 + t];
                qv[k][t * 4 + 0] = v.x; qv[k][t * 4 + 1] = v.y;
                qv[k][t * 4 + 2] = v.z; qv[k][t * 4 + 3] = v.w;
            }
        }

        float q[KK][EE], ke[KK][EE], v0[EE];
#pragma unroll
        for (int k = 0; k < KK; ++k)
#pragma unroll
            for (int e = 0; e < EE; ++e) {
                q[k][e]  = qv[k][e]      + sBC[k * NC + e];
                ke[k][e] = qv[k][10 + e] + sBC[k * NC + 10 + e];
            }
#pragma unroll
        for (int e = 0; e < EE; ++e) v0[e] = qv[0][20 + e] + sBC[20 + e];

        float w0o[EE];
#pragma unroll
        for (int e = 0; e < EE; ++e) w0o[e] = 0.f;
        const float inv_sqrtE = 0.31622776601683794f;   // 1/sqrt(10)
        float* attn_row = out_attn + (size_t)b * (EE * EE);

#pragma unroll
        for (int l = 0; l < EE; ++l) {
            float col[EE];
#pragma unroll
            for (int e = 0; e < EE; ++e)
                col[e] = (q[0][e] * ke[0][l] + q[1][e] * ke[1][l] +
                          q[2][e] * ke[2][l] + q[3][e] * ke[3][l]) * inv_sqrtE;
            float mx = col[0];
#pragma unroll
            for (int e = 1; e < EE; ++e) mx = fmaxf(mx, col[e]);
            float p[EE], s = 0.f;
#pragma unroll
            for (int e = 0; e < EE; ++e) { p[e] = __expf(col[e] - mx); s += p[e]; }
            const float is = 1.f / s;
#pragma unroll
            for (int e = 0; e < EE; ++e) {
                p[e] *= is;
                attn_row[e * EE + l] = p[e];
                w0o[e] += p[e] * v0[l];
            }
        }

        float oacc[CC];
#pragma unroll
        for (int c = 0; c < CC; ++c) oacc[c] = 0.f;
#pragma unroll
        for (int k = 0; k < KK; ++k) {
            float lg[CC];
#pragma unroll
            for (int c = 0; c < CC; ++c) {
                float s2 = bfin[k * CC + c];
#pragma unroll
                for (int e = 0; e < EE; ++e)
                    s2 += w0o[e] * Wfin[k * CC * EE + c * EE + e];
                lg[c] = s2;
            }
            float mx = lg[0];
#pragma unroll
            for (int c = 1; c < CC; ++c) mx = fmaxf(mx, lg[c]);
            float p[CC], s = 0.f;
#pragma unroll
            for (int c = 0; c < CC; ++c) { p[c] = __expf(lg[c] - mx); s += p[c]; }
            const float is = 1.f / s;
#pragma unroll
            for (int c = 0; c < CC; ++c) oacc[c] += p[c] * is;
        }
        float* outr = out_outputs + (size_t)b * CC;
#pragma unroll
        for (int c = 0; c < CC; ++c) outr[c] = oacc[c] * 0.25f;
    }
}

// ---------------------------------------------------------------------------
extern "C" void kernel_launch(void* const* d_in, const int* in_sizes, int n_in,
                              void* d_out, int out_size) {
    const float* w0   = (const float*)d_in[0];
    const float* w1   = (const float*)d_in[1];
    const float* w2   = (const float*)d_in[2];
    const float* w3   = (const float*)d_in[3];
    const float* Wlin = (const float*)d_in[4];
    const float* blin = (const float*)d_in[5];
    const float* Wq   = (const float*)d_in[6];
    const float* bq   = (const float*)d_in[7];
    const float* Wk   = (const float*)d_in[8];
    const float* bk   = (const float*)d_in[9];
    const float* Wv   = (const float*)d_in[10];
    const float* bv   = (const float*)d_in[11];
    const float* Wfin = (const float*)d_in[12];
    const float* bfin = (const float*)d_in[13];

    float* out      = (float*)d_out;
    float* out_attn = out + (size_t)BB * CC;

    cudaFuncSetAttribute(fused_main, cudaFuncAttributeMaxDynamicSharedMemorySize, SMEM_BYTES);

    precompute_part<<<dim3(4, 32, 8), 128>>>(Wlin, Wq, Wk, Wv);
    finalize<<<528, 256>>>(blin, Wq, bq, Wk, bk, Wv, bv);
    fused_main<<<BB / 128, 256, SMEM_BYTES>>>(w0, w1, w2, w3, Wfin, bfin, out, out_attn);
}

// round 12
// speedup vs baseline: 4.0616x; 1.0406x over previous
#include <cuda_runtime.h>
#include <cuda_bf16.h>
#include <math.h>
#include <cstdint>

// Problem constants
#define BB   32768
#define FF   1024
#define HH   512
#define EE   10
#define CC   10
#define KK   4
#define KC   64        // K chunk per iteration
#define NKC  (FF/KC)   // 16
#define NIT  (KK*NKC)  // 64 iterations

// A/B smem row stride: 72 bf16 = 144 bytes (16B-aligned, conflict-free ldmatrix)
#define RST  144

// ---------------- device scratch (allocation-free) ----------------
__device__ float g_part[16 * KK * 32 * FF];     // 16 j-slice partials
__device__ float g_bc[KK * 32];                 // folded biases
// B tiles bf16 hi/lo, padded row-major image: [k][kc][hi 32x72 | lo 32x72]
__device__ __align__(16) __nv_bfloat16 g_Wb[KK * NKC * 2 * 32 * 72];
// qkv staging TRANSPOSED: [c][b], c = k*32+col (16 MB)
__device__ __align__(16) float g_qkv[(size_t)128 * BB];

// ---------------- PTX helpers ----------------
__device__ __forceinline__ uint32_t smem_u32(const void* p) {
    uint32_t a;
    asm("{ .reg .u64 t; cvta.to.shared.u64 t, %1; cvt.u32.u64 %0, t; }" : "=r"(a) : "l"(p));
    return a;
}
__device__ __forceinline__ void ldsm4(uint32_t* r, uint32_t addr) {
    asm volatile("ldmatrix.sync.aligned.m8n8.x4.shared.b16 {%0,%1,%2,%3}, [%4];"
        : "=r"(r[0]), "=r"(r[1]), "=r"(r[2]), "=r"(r[3]) : "r"(addr));
}
__device__ __forceinline__ void mma_bf16(float* d, const uint32_t* a, const uint32_t* b) {
    asm volatile("mma.sync.aligned.m16n8k16.row.col.f32.bf16.bf16.f32 "
        "{%0,%1,%2,%3}, {%4,%5,%6,%7}, {%8,%9}, {%0,%1,%2,%3};"
        : "+f"(d[0]), "+f"(d[1]), "+f"(d[2]), "+f"(d[3])
        : "r"(a[0]), "r"(a[1]), "r"(a[2]), "r"(a[3]), "r"(b[0]), "r"(b[1]));
}
#define CVT_BF16X2(res, a, b) \
    asm("cvt.rn.satfinite.bf16x2.f32 %0, %1, %2;" : "=r"(res) : "f"(b), "f"(a))

// ---------------------------------------------------------------------------
// Kernel 1: partial fold over 16 j-slices of 32.
// grid (4 k, 32 fchunk, 16 jslice) x 128 threads
// ---------------------------------------------------------------------------
__global__ void precompute_part(const float* __restrict__ Wlin,
                                const float* __restrict__ Wq,
                                const float* __restrict__ Wk,
                                const float* __restrict__ Wv) {
    __shared__ float sS[32 * 32];
    const int k = blockIdx.x, fc = blockIdx.y, js = blockIdx.z;
    const int tid = threadIdx.x;

#pragma unroll
    for (int t = 0; t < 8; ++t) {
        int idx = tid + t * 128;       // 0..1023
        int c = idx >> 5;
        int j = idx & 31;
        int jj = js * 32 + j;
        float v = 0.f;
        if (c < 10)                v = Wq[(k * 10 + c) * 512 + jj];
        else if (c < 20)           v = Wk[(k * 10 + (c - 10)) * 512 + jj];
        else if (c < 30 && k == 0) v = Wv[(c - 20) * 512 + jj];
        sS[c * 32 + j] = v;
    }
    __syncthreads();

    const int f  = fc * 32 + (tid & 31);
    const int cg = tid >> 5;
    float acc[8];
#pragma unroll
    for (int i = 0; i < 8; ++i) acc[i] = 0.f;
    const float* wl = Wlin + ((size_t)k * HH + js * 32) * FF + f;
#pragma unroll
    for (int jb = 0; jb < 32; jb += 8) {
        float wv[8];
#pragma unroll
        for (int t = 0; t < 8; ++t) wv[t] = wl[(size_t)(jb + t) * FF];
#pragma unroll
        for (int t = 0; t < 8; ++t)
#pragma unroll
            for (int i = 0; i < 8; ++i)
                acc[i] += wv[t] * sS[(cg * 8 + i) * 32 + jb + t];
    }
#pragma unroll
    for (int i = 0; i < 8; ++i)
        g_part[(((size_t)js * KK + k) * 32 + cg * 8 + i) * FF + f] = acc[i];
}

// ---------------------------------------------------------------------------
// Kernel 2 (fused finalize): blocks 0..511 reduce 16 partials -> bf16 hi/lo
// B images; blocks 512..527 fold biases (one warp per (k,c)).
// ---------------------------------------------------------------------------
__global__ void finalize(const float* __restrict__ blin,
                         const float* __restrict__ Wq, const float* __restrict__ bq,
                         const float* __restrict__ Wk, const float* __restrict__ bk,
                         const float* __restrict__ Wv, const float* __restrict__ bv) {
    const int blk = blockIdx.x;
    if (blk < 512) {
        int idx = blk * 256 + threadIdx.x;     // < 131072
        const int S = KK * 32 * FF;
        float s = 0.f;
#pragma unroll
        for (int js = 0; js < 16; ++js) s += g_part[(size_t)js * S + idx];
        int k  = idx >> 15;
        int c  = (idx >> 10) & 31;
        int f  = idx & 1023;
        int kc = f >> 6;                        // 0..15
        int fl = f & 63;
        __nv_bfloat16 h = __float2bfloat16(s);
        __nv_bfloat16 l = __float2bfloat16(s - __bfloat162float(h));
        size_t base = (size_t)(k * NKC + kc) * (2 * 32 * 72);
        g_Wb[base + c * 72 + fl]           = h;
        g_Wb[base + 32 * 72 + c * 72 + fl] = l;
    } else {
        int gw   = (blk - 512) * 8 + (threadIdx.x >> 5);   // 0..127
        int lane = threadIdx.x & 31;
        int k = gw >> 5, c = gw & 31;
        const float* W = nullptr;
        float base = 0.f;
        if (c < 10)                { W = Wq + (k * 10 + c) * 512;        base = bq[k * 10 + c]; }
        else if (c < 20)           { W = Wk + (k * 10 + (c - 10)) * 512; base = bk[k * 10 + (c - 10)]; }
        else if (c < 30 && k == 0) { W = Wv + (c - 20) * 512;            base = bv[c - 20]; }
        float s = 0.f;
        if (W) {
            const float* bl = blin + k * 512;
#pragma unroll
            for (int t = 0; t < 16; ++t) s += bl[lane + 32 * t] * W[lane + 32 * t];
        }
#pragma unroll
        for (int o = 16; o; o >>= 1) s += __shfl_xor_sync(0xffffffffu, s, o);
        if (lane == 0) g_bc[gw] = W ? (base + s) : 0.f;
    }
}

// ---------------------------------------------------------------------------
// Kernel 3: fused HMMA GEMM + attention, double-buffered (KC=64).
// 256 blocks x 256 threads; warps 0..3 MMA (32 rows each), all warps load/convert.
// SMEM: [0..512) bias; buffers at 1024 + p*46080, each:
//   Ahi [0..18432)  Alo [18432..36864)  Bhi [36864..41472)  Blo [41472..46080)
// attn staging (phase 2) reuses [1024..52224).
// ---------------------------------------------------------------------------
#define S_BC     0
#define BUF_BASE 1024
#define BUF_SZ   46080
#define A_LO_O   18432
#define B_HI_O   36864
#define B_LO_O   41472
#define SMEM_BYTES (BUF_BASE + 2 * BUF_SZ)   // 93184

__global__ __launch_bounds__(256, 2)
void fused_main(const float* __restrict__ w0, const float* __restrict__ w1,
                const float* __restrict__ w2, const float* __restrict__ w3,
                const float* __restrict__ Wfin, const float* __restrict__ bfin,
                float* __restrict__ out_outputs, float* __restrict__ out_attn) {
    extern __shared__ char smem[];
    const uint32_t sb = smem_u32(smem);
    const int tid  = threadIdx.x;
    const int wid  = tid >> 5;
    const int lane = tid & 31;
    const int b0   = blockIdx.x * 128;

    // ldmatrix intra-buffer offsets
    const uint32_t aRowOff = (uint32_t)((wid * 32 + (lane & 7) + ((lane >> 3) & 1) * 8) * RST
                                        + (lane >> 4) * 16);
    const uint32_t bRow0   = (uint32_t)((((lane >> 4) & 1) * 8 + (lane & 7)) * RST
                                        + ((lane >> 3) & 1) * 16);

    // iteration loaders (A fp32 regs + B image regs)
    auto load_iter = [&](int j, float4* va, uint4* vb) {
        const int k2 = j >> 4, kc2 = j & 15;
        const float* wk = (k2 == 0) ? w0 : (k2 == 1) ? w1 : (k2 == 2) ? w2 : w3;
#pragma unroll
        for (int u = 0; u < 8; ++u) {
            int idx = tid + u * 256;            // 0..2047
            int row = idx >> 4, f4 = idx & 15;
            va[u] = *(const float4*)(wk + (size_t)(b0 + row) * FF + kc2 * KC + f4 * 4);
        }
        const uint4* srcB = (const uint4*)(g_Wb + (size_t)(k2 * NKC + kc2) * (2 * 32 * 72));
        vb[0] = srcB[tid];
        vb[1] = srcB[tid + 256];
        if (tid < 64) vb[2] = srcB[tid + 512];
    };
    auto convert_sts = [&](char* bb, const float4* va, const uint4* vb) {
        uint4* dstB = (uint4*)(bb + B_HI_O);
        dstB[tid]       = vb[0];
        dstB[tid + 256] = vb[1];
        if (tid < 64) dstB[tid + 512] = vb[2];
#pragma unroll
        for (int u = 0; u < 8; ++u) {
            int idx = tid + u * 256;
            int row = idx >> 4, f4 = idx & 15;
            int off = row * RST + f4 * 8;
            float4 v = va[u];
            uint32_t hp0, hp1, lp0, lp1;
            CVT_BF16X2(hp0, v.x, v.y);
            CVT_BF16X2(hp1, v.z, v.w);
            float h0 = __uint_as_float(hp0 << 16);
            float h1 = __uint_as_float(hp0 & 0xffff0000u);
            float h2 = __uint_as_float(hp1 << 16);
            float h3 = __uint_as_float(hp1 & 0xffff0000u);
            CVT_BF16X2(lp0, v.x - h0, v.y - h1);
            CVT_BF16X2(lp1, v.z - h2, v.w - h3);
            *(uint2*)(bb + off)          = make_uint2(hp0, hp1);
            *(uint2*)(bb + A_LO_O + off) = make_uint2(lp0, lp1);
        }
    };

    float acc[2][4][4];
#pragma unroll
    for (int mt = 0; mt < 2; ++mt)
#pragma unroll
        for (int nt = 0; nt < 4; ++nt)
#pragma unroll
            for (int i = 0; i < 4; ++i) acc[mt][nt][i] = 0.f;

    // prologue: fill buffer 0
    {
        float4 va[8]; uint4 vb[3];
        load_iter(0, va, vb);
        convert_sts(smem + BUF_BASE, va, vb);
        if (tid < 128) ((float*)(smem + S_BC))[tid] = g_bc[tid];
    }
    __syncthreads();

    for (int i = 0; i < NIT; ++i) {
        const uint32_t bufo = sb + BUF_BASE + (uint32_t)(i & 1) * BUF_SZ;
        const bool hn = (i < NIT - 1);
        float4 va[8]; uint4 vb[3];

        if (wid < 4) {
            const bool do3 = (i >> 4) == 0;     // k==0 has v columns (nt3)
#pragma unroll
            for (int s = 0; s < 4; ++s) {
                const uint32_t so = bufo + (uint32_t)(s * 32);
                uint32_t ah0[4], ah1[4], al0[4], al1[4], bh[8], bl[8];
                ldsm4(ah0, so + aRowOff);
                ldsm4(ah1, so + aRowOff + 16 * RST);
                ldsm4(al0, so + aRowOff + A_LO_O);
                ldsm4(al1, so + aRowOff + A_LO_O + 16 * RST);
                ldsm4(bh,     so + B_HI_O + bRow0);
                ldsm4(bh + 4, so + B_HI_O + bRow0 + 16 * RST);
                ldsm4(bl,     so + B_LO_O + bRow0);
                ldsm4(bl + 4, so + B_LO_O + bRow0 + 16 * RST);
                // m-tile 0
                mma_bf16(acc[0][0], ah0, bh + 0);
                mma_bf16(acc[0][0], ah0, bl + 0);
                mma_bf16(acc[0][0], al0, bh + 0);
                mma_bf16(acc[0][1], ah0, bh + 2);
                mma_bf16(acc[0][1], ah0, bl + 2);
                mma_bf16(acc[0][1], al0, bh + 2);
                mma_bf16(acc[0][2], ah0, bh + 4);
                mma_bf16(acc[0][2], ah0, bl + 4);
                mma_bf16(acc[0][2], al0, bh + 4);
                if (do3) {
                    mma_bf16(acc[0][3], ah0, bh + 6);
                    mma_bf16(acc[0][3], ah0, bl + 6);
                    mma_bf16(acc[0][3], al0, bh + 6);
                }
                // m-tile 1
                mma_bf16(acc[1][0], ah1, bh + 0);
                mma_bf16(acc[1][0], ah1, bl + 0);
                mma_bf16(acc[1][0], al1, bh + 0);
                mma_bf16(acc[1][1], ah1, bh + 2);
                mma_bf16(acc[1][1], ah1, bl + 2);
                mma_bf16(acc[1][1], al1, bh + 2);
                mma_bf16(acc[1][2], ah1, bh + 4);
                mma_bf16(acc[1][2], ah1, bl + 4);
                mma_bf16(acc[1][2], al1, bh + 4);
                if (do3) {
                    mma_bf16(acc[1][3], ah1, bh + 6);
                    mma_bf16(acc[1][3], ah1, bl + 6);
                    mma_bf16(acc[1][3], al1, bh + 6);
                }
            }
            // dump at k boundary (transposed [c][b]; sector-dense writes)
            if ((i & 15) == 15) {
                const int k  = i >> 4;
                const int rr = wid * 32 + (lane >> 2);
                const int cb = (lane & 3) * 2;
#pragma unroll
                for (int mt = 0; mt < 2; ++mt) {
#pragma unroll
                    for (int nt = 0; nt < 4; ++nt) {
                        if (k > 0 && nt == 3) continue;
                        const int c = k * 32 + nt * 8 + cb;
                        const int r = b0 + rr + mt * 16;
                        g_qkv[(size_t)c * BB + r]           = acc[mt][nt][0];
                        g_qkv[(size_t)(c + 1) * BB + r]     = acc[mt][nt][1];
                        g_qkv[(size_t)c * BB + r + 8]       = acc[mt][nt][2];
                        g_qkv[(size_t)(c + 1) * BB + r + 8] = acc[mt][nt][3];
#pragma unroll
                        for (int q = 0; q < 4; ++q) acc[mt][nt][q] = 0.f;
                    }
                }
            }
            if (hn) load_iter(i + 1, va, vb);
        } else {
            // producer warps: issue next-iter loads immediately (overlap MMA)
            if (hn) load_iter(i + 1, va, vb);
        }

        if (hn) convert_sts(smem + BUF_BASE + ((i + 1) & 1) * BUF_SZ, va, vb);
        __syncthreads();
    }

    // ---- phase 2: per-row attention (threads 0..127), attn staged in smem ----
    float* sAttn = (float*)(smem + BUF_BASE);   // 128 rows x 100 floats = 51.2 KB
    if (tid < 128) {
        const int b = b0 + tid;
        const float* sBC = (const float*)(smem + S_BC);

        float q[KK][EE], ke[KK][EE], v0[EE];
#pragma unroll
        for (int k = 0; k < KK; ++k)
#pragma unroll
            for (int e = 0; e < EE; ++e) {
                q[k][e]  = g_qkv[(size_t)(k * 32 + e) * BB + b]      + sBC[k * 32 + e];
                ke[k][e] = g_qkv[(size_t)(k * 32 + 10 + e) * BB + b] + sBC[k * 32 + 10 + e];
            }
#pragma unroll
        for (int e = 0; e < EE; ++e)
            v0[e] = g_qkv[(size_t)(20 + e) * BB + b] + sBC[20 + e];

        float w0o[EE];
#pragma unroll
        for (int e = 0; e < EE; ++e) w0o[e] = 0.f;
        const float inv_sqrtE = 0.31622776601683794f;   // 1/sqrt(10)
        float* arow = sAttn + tid * 100;

#pragma unroll
        for (int l = 0; l < EE; ++l) {
            float col[EE];
#pragma unroll
            for (int e = 0; e < EE; ++e)
                col[e] = (q[0][e] * ke[0][l] + q[1][e] * ke[1][l] +
                          q[2][e] * ke[2][l] + q[3][e] * ke[3][l]) * inv_sqrtE;
            float mx = col[0];
#pragma unroll
            for (int e = 1; e < EE; ++e) mx = fmaxf(mx, col[e]);
            float p[EE], s = 0.f;
#pragma unroll
            for (int e = 0; e < EE; ++e) { p[e] = __expf(col[e] - mx); s += p[e]; }
            const float is = 1.f / s;
#pragma unroll
            for (int e = 0; e < EE; ++e) {
                p[e] *= is;
                arow[e * EE + l] = p[e];
                w0o[e] += p[e] * v0[l];
            }
        }

        float oacc[CC];
#pragma unroll
        for (int c = 0; c < CC; ++c) oacc[c] = 0.f;
#pragma unroll
        for (int k = 0; k < KK; ++k) {
            float lg[CC];
#pragma unroll
            for (int c = 0; c < CC; ++c) {
                float s2 = bfin[k * CC + c];
#pragma unroll
                for (int e = 0; e < EE; ++e)
                    s2 += w0o[e] * Wfin[k * CC * EE + c * EE + e];
                lg[c] = s2;
            }
            float mx = lg[0];
#pragma unroll
            for (int c = 1; c < CC; ++c) mx = fmaxf(mx, lg[c]);
            float p[CC], s = 0.f;
#pragma unroll
            for (int c = 0; c < CC; ++c) { p[c] = __expf(lg[c] - mx); s += p[c]; }
            const float is = 1.f / s;
#pragma unroll
            for (int c = 0; c < CC; ++c) oacc[c] += p[c] * is;
        }
        float* outr = out_outputs + (size_t)b * CC;
#pragma unroll
        for (int c = 0; c < CC; ++c) outr[c] = oacc[c] * 0.25f;
    }
    __syncthreads();

    // dense coalesced attn writeback: 128 rows x 100 floats = 3200 float4
    {
        const float4* src = (const float4*)sAttn;
        float4* dst = (float4*)(out_attn + (size_t)b0 * 100);
        for (int t = tid; t < 3200; t += 256) dst[t] = src[t];
    }
}

// ---------------------------------------------------------------------------
extern "C" void kernel_launch(void* const* d_in, const int* in_sizes, int n_in,
                              void* d_out, int out_size) {
    const float* w0   = (const float*)d_in[0];
    const float* w1   = (const float*)d_in[1];
    const float* w2   = (const float*)d_in[2];
    const float* w3   = (const float*)d_in[3];
    const float* Wlin = (const float*)d_in[4];
    const float* blin = (const float*)d_in[5];
    const float* Wq   = (const float*)d_in[6];
    const float* bq   = (const float*)d_in[7];
    const float* Wk   = (const float*)d_in[8];
    const float* bk   = (const float*)d_in[9];
    const float* Wv   = (const float*)d_in[10];
    const float* bv   = (const float*)d_in[11];
    const float* Wfin = (const float*)d_in[12];
    const float* bfin = (const float*)d_in[13];

    float* out      = (float*)d_out;
    float* out_attn = out + (size_t)BB * CC;

    cudaFuncSetAttribute(fused_main, cudaFuncAttributeMaxDynamicSharedMemorySize, SMEM_BYTES);

    precompute_part<<<dim3(4, 32, 16), 128>>>(Wlin, Wq, Wk, Wv);
    finalize<<<528, 256>>>(blin, Wq, bq, Wk, bk, Wv, bv);
    fused_main<<<BB / 128, 256, SMEM_BYTES>>>(w0, w1, w2, w3, Wfin, bfin, out, out_attn);
}

// round 13
// speedup vs baseline: 4.8454x; 1.1930x over previous
#include <cuda_runtime.h>
#include <cuda_bf16.h>
#include <math.h>
#include <cstdint>

// Problem constants
#define BB   32768
#define FF   1024
#define HH   512
#define EE   10
#define CC   10
#define KK   4
#define KC   64        // K chunk per iteration
#define NKC  (FF/KC)   // 16
#define NIT  (KK*NKC)  // 64 iterations

// A/B smem row stride: 72 bf16 = 144 bytes (16B-aligned, conflict-free ldmatrix)
#define RST  144

// ---------------- device scratch (allocation-free) ----------------
__device__ float g_part[16 * KK * 32 * FF];     // 16 j-slice partials
__device__ float g_bc[KK * 32];                 // folded biases
// B tiles bf16 hi/lo, padded row-major image: [k][kc][hi 32x72 | lo 32x72] = 9216 B each
__device__ __align__(16) __nv_bfloat16 g_Wb[KK * NKC * 2 * 32 * 72];
// qkv staging TRANSPOSED: [c][b], c = k*32+col (16 MB)
__device__ __align__(16) float g_qkv[(size_t)128 * BB];

// ---------------- PTX helpers ----------------
__device__ __forceinline__ uint32_t smem_u32(const void* p) {
    uint32_t a;
    asm("{ .reg .u64 t; cvta.to.shared.u64 t, %1; cvt.u32.u64 %0, t; }" : "=r"(a) : "l"(p));
    return a;
}
__device__ __forceinline__ void ldsm4(uint32_t* r, uint32_t addr) {
    asm volatile("ldmatrix.sync.aligned.m8n8.x4.shared.b16 {%0,%1,%2,%3}, [%4];"
        : "=r"(r[0]), "=r"(r[1]), "=r"(r[2]), "=r"(r[3]) : "r"(addr));
}
__device__ __forceinline__ void mma_bf16(float* d, const uint32_t* a, const uint32_t* b) {
    asm volatile("mma.sync.aligned.m16n8k16.row.col.f32.bf16.bf16.f32 "
        "{%0,%1,%2,%3}, {%4,%5,%6,%7}, {%8,%9}, {%0,%1,%2,%3};"
        : "+f"(d[0]), "+f"(d[1]), "+f"(d[2]), "+f"(d[3])
        : "r"(a[0]), "r"(a[1]), "r"(a[2]), "r"(a[3]), "r"(b[0]), "r"(b[1]));
}
__device__ __forceinline__ void cp_async16(uint32_t sdst, const void* gsrc) {
    asm volatile("cp.async.ca.shared.global [%0], [%1], 16;"
        :: "r"(sdst), "l"(gsrc) : "memory");
}
#define CP_COMMIT() asm volatile("cp.async.commit_group;" ::: "memory")
#define CP_WAIT0()  asm volatile("cp.async.wait_group 0;" ::: "memory")
#define CVT_BF16X2(res, a, b) \
    asm("cvt.rn.satfinite.bf16x2.f32 %0, %1, %2;" : "=r"(res) : "f"(b), "f"(a))

// ---------------------------------------------------------------------------
// Kernel 1: partial fold over 16 j-slices of 32.
// grid (4 k, 32 fchunk, 16 jslice) x 128 threads
// ---------------------------------------------------------------------------
__global__ void precompute_part(const float* __restrict__ Wlin,
                                const float* __restrict__ Wq,
                                const float* __restrict__ Wk,
                                const float* __restrict__ Wv) {
    __shared__ float sS[32 * 32];
    const int k = blockIdx.x, fc = blockIdx.y, js = blockIdx.z;
    const int tid = threadIdx.x;

#pragma unroll
    for (int t = 0; t < 8; ++t) {
        int idx = tid + t * 128;       // 0..1023
        int c = idx >> 5;
        int j = idx & 31;
        int jj = js * 32 + j;
        float v = 0.f;
        if (c < 10)                v = Wq[(k * 10 + c) * 512 + jj];
        else if (c < 20)           v = Wk[(k * 10 + (c - 10)) * 512 + jj];
        else if (c < 30 && k == 0) v = Wv[(c - 20) * 512 + jj];
        sS[c * 32 + j] = v;
    }
    __syncthreads();

    const int f  = fc * 32 + (tid & 31);
    const int cg = tid >> 5;
    float acc[8];
#pragma unroll
    for (int i = 0; i < 8; ++i) acc[i] = 0.f;
    const float* wl = Wlin + ((size_t)k * HH + js * 32) * FF + f;
#pragma unroll
    for (int jb = 0; jb < 32; jb += 8) {
        float wv[8];
#pragma unroll
        for (int t = 0; t < 8; ++t) wv[t] = wl[(size_t)(jb + t) * FF];
#pragma unroll
        for (int t = 0; t < 8; ++t)
#pragma unroll
            for (int i = 0; i < 8; ++i)
                acc[i] += wv[t] * sS[(cg * 8 + i) * 32 + jb + t];
    }
#pragma unroll
    for (int i = 0; i < 8; ++i)
        g_part[(((size_t)js * KK + k) * 32 + cg * 8 + i) * FF + f] = acc[i];
}

// ---------------------------------------------------------------------------
// Kernel 2 (fused finalize): blocks 0..511 reduce 16 partials -> bf16 hi/lo
// B images; blocks 512..527 fold biases (one warp per (k,c)).
// ---------------------------------------------------------------------------
__global__ void finalize(const float* __restrict__ blin,
                         const float* __restrict__ Wq, const float* __restrict__ bq,
                         const float* __restrict__ Wk, const float* __restrict__ bk,
                         const float* __restrict__ Wv, const float* __restrict__ bv) {
    const int blk = blockIdx.x;
    if (blk < 512) {
        int idx = blk * 256 + threadIdx.x;     // < 131072
        const int S = KK * 32 * FF;
        float s = 0.f;
#pragma unroll
        for (int js = 0; js < 16; ++js) s += g_part[(size_t)js * S + idx];
        int k  = idx >> 15;
        int c  = (idx >> 10) & 31;
        int f  = idx & 1023;
        int kc = f >> 6;                        // 0..15
        int fl = f & 63;
        __nv_bfloat16 h = __float2bfloat16(s);
        __nv_bfloat16 l = __float2bfloat16(s - __bfloat162float(h));
        size_t base = (size_t)(k * NKC + kc) * (2 * 32 * 72);
        g_Wb[base + c * 72 + fl]           = h;
        g_Wb[base + 32 * 72 + c * 72 + fl] = l;
    } else {
        int gw   = (blk - 512) * 8 + (threadIdx.x >> 5);   // 0..127
        int lane = threadIdx.x & 31;
        int k = gw >> 5, c = gw & 31;
        const float* W = nullptr;
        float base = 0.f;
        if (c < 10)                { W = Wq + (k * 10 + c) * 512;        base = bq[k * 10 + c]; }
        else if (c < 20)           { W = Wk + (k * 10 + (c - 10)) * 512; base = bk[k * 10 + (c - 10)]; }
        else if (c < 30 && k == 0) { W = Wv + (c - 20) * 512;            base = bv[c - 20]; }
        float s = 0.f;
        if (W) {
            const float* bl = blin + k * 512;
#pragma unroll
            for (int t = 0; t < 16; ++t) s += bl[lane + 32 * t] * W[lane + 32 * t];
        }
#pragma unroll
        for (int o = 16; o; o >>= 1) s += __shfl_xor_sync(0xffffffffu, s, o);
        if (lane == 0) g_bc[gw] = W ? (base + s) : 0.f;
    }
}

// ---------------------------------------------------------------------------
// Kernel 3: fused HMMA GEMM + attention. Depth-2 pipelined double buffer.
// 256 blocks x 256 threads; warps 0..3 MMA (32 rows each), all warps convert.
// Registers va[] hold A data for iteration i+1 during iteration i; the LDG for
// i+2 issues at the end of iteration i. B arrives via cp.async.
// SMEM: [0..512) bias; buffers at 1024 + p*46080:
//   Ahi [0..18432)  Alo [18432..36864)  Bhi [36864..41472)  Blo [41472..46080)
// attn staging (phase 2) reuses [1024..52224).
// ---------------------------------------------------------------------------
#define S_BC     0
#define BUF_BASE 1024
#define BUF_SZ   46080
#define A_LO_O   18432
#define B_HI_O   36864
#define SMEM_BYTES (BUF_BASE + 2 * BUF_SZ)   // 93184

__global__ __launch_bounds__(256, 2)
void fused_main(const float* __restrict__ w0, const float* __restrict__ w1,
                const float* __restrict__ w2, const float* __restrict__ w3,
                const float* __restrict__ Wfin, const float* __restrict__ bfin,
                float* __restrict__ out_outputs, float* __restrict__ out_attn) {
    extern __shared__ char smem[];
    const uint32_t sb = smem_u32(smem);
    const int tid  = threadIdx.x;
    const int wid  = tid >> 5;
    const int lane = tid & 31;
    const int b0   = blockIdx.x * 128;

    // ldmatrix intra-buffer offsets
    const uint32_t aRowOff = (uint32_t)((wid * 32 + (lane & 7) + ((lane >> 3) & 1) * 8) * RST
                                        + (lane >> 4) * 16);
    const uint32_t bRow0   = (uint32_t)((((lane >> 4) & 1) * 8 + (lane & 7)) * RST
                                        + ((lane >> 3) & 1) * 16);

    // B image cp.async: 9216 B = 576 x 16B chunks, all 256 threads
    auto cpasync_B = [&](int j, uint32_t bufbase /*smem addr*/) {
        const char* src = (const char*)g_Wb + (size_t)j * 9216;
        uint32_t dst = bufbase + B_HI_O;
        cp_async16(dst + (uint32_t)tid * 16,         src + (size_t)tid * 16);
        cp_async16(dst + (uint32_t)(tid + 256) * 16, src + (size_t)(tid + 256) * 16);
        if (tid < 64)
            cp_async16(dst + (uint32_t)(tid + 512) * 16, src + (size_t)(tid + 512) * 16);
        CP_COMMIT();
    };
    // A loads: 2048 float4, 8 per thread
    auto load_A = [&](int j, float4* va) {
        const int k2 = j >> 4, kc2 = j & 15;
        const float* wk = (k2 == 0) ? w0 : (k2 == 1) ? w1 : (k2 == 2) ? w2 : w3;
#pragma unroll
        for (int u = 0; u < 8; ++u) {
            int idx = tid + u * 256;            // 0..2047
            int row = idx >> 4, f4 = idx & 15;
            va[u] = *(const float4*)(wk + (size_t)(b0 + row) * FF + kc2 * KC + f4 * 4);
        }
    };
    auto convert_sts = [&](char* bb, const float4* va) {
#pragma unroll
        for (int u = 0; u < 8; ++u) {
            int idx = tid + u * 256;
            int row = idx >> 4, f4 = idx & 15;
            int off = row * RST + f4 * 8;
            float4 v = va[u];
            uint32_t hp0, hp1, lp0, lp1;
            CVT_BF16X2(hp0, v.x, v.y);
            CVT_BF16X2(hp1, v.z, v.w);
            float h0 = __uint_as_float(hp0 << 16);
            float h1 = __uint_as_float(hp0 & 0xffff0000u);
            float h2 = __uint_as_float(hp1 << 16);
            float h3 = __uint_as_float(hp1 & 0xffff0000u);
            CVT_BF16X2(lp0, v.x - h0, v.y - h1);
            CVT_BF16X2(lp1, v.z - h2, v.w - h3);
            *(uint2*)(bb + off)          = make_uint2(hp0, hp1);
            *(uint2*)(bb + A_LO_O + off) = make_uint2(lp0, lp1);
        }
    };

    float acc[2][4][4];
#pragma unroll
    for (int mt = 0; mt < 2; ++mt)
#pragma unroll
        for (int nt = 0; nt < 4; ++nt)
#pragma unroll
            for (int i = 0; i < 4; ++i) acc[mt][nt][i] = 0.f;

    float4 va[8];   // pipeline staging: holds A data for iteration i+1

    // ---- prologue: B0 + A0 into buf0; preload A1 into va ----
    cpasync_B(0, sb + BUF_BASE);
    load_A(0, va);
    convert_sts(smem + BUF_BASE, va);
    load_A(1, va);
    if (tid < 128) ((float*)(smem + S_BC))[tid] = g_bc[tid];
    CP_WAIT0();
    __syncthreads();

    for (int i = 0; i < NIT; ++i) {
        const uint32_t bufo = sb + BUF_BASE + (uint32_t)(i & 1) * BUF_SZ;
        const bool hn = (i < NIT - 1);

        if (hn) cpasync_B(i + 1, sb + BUF_BASE + (uint32_t)((i + 1) & 1) * BUF_SZ);

        if (wid < 4) {
            const bool do3 = (i >> 4) == 0;     // k==0 has v columns (nt3)
#pragma unroll
            for (int s = 0; s < 4; ++s) {
                const uint32_t so = bufo + (uint32_t)(s * 32);
                uint32_t ah0[4], ah1[4], al0[4], al1[4], bh[8], bl[8];
                ldsm4(ah0, so + aRowOff);
                ldsm4(ah1, so + aRowOff + 16 * RST);
                ldsm4(al0, so + aRowOff + A_LO_O);
                ldsm4(al1, so + aRowOff + A_LO_O + 16 * RST);
                ldsm4(bh,     so + B_HI_O + bRow0);
                ldsm4(bh + 4, so + B_HI_O + bRow0 + 16 * RST);
                ldsm4(bl,     so + B_HI_O + 4608 + bRow0);
                ldsm4(bl + 4, so + B_HI_O + 4608 + bRow0 + 16 * RST);
                // m-tile 0
                mma_bf16(acc[0][0], ah0, bh + 0);
                mma_bf16(acc[0][0], ah0, bl + 0);
                mma_bf16(acc[0][0], al0, bh + 0);
                mma_bf16(acc[0][1], ah0, bh + 2);
                mma_bf16(acc[0][1], ah0, bl + 2);
                mma_bf16(acc[0][1], al0, bh + 2);
                mma_bf16(acc[0][2], ah0, bh + 4);
                mma_bf16(acc[0][2], ah0, bl + 4);
                mma_bf16(acc[0][2], al0, bh + 4);
                if (do3) {
                    mma_bf16(acc[0][3], ah0, bh + 6);
                    mma_bf16(acc[0][3], ah0, bl + 6);
                    mma_bf16(acc[0][3], al0, bh + 6);
                }
                // m-tile 1
                mma_bf16(acc[1][0], ah1, bh + 0);
                mma_bf16(acc[1][0], ah1, bl + 0);
                mma_bf16(acc[1][0], al1, bh + 0);
                mma_bf16(acc[1][1], ah1, bh + 2);
                mma_bf16(acc[1][1], ah1, bl + 2);
                mma_bf16(acc[1][1], al1, bh + 2);
                mma_bf16(acc[1][2], ah1, bh + 4);
                mma_bf16(acc[1][2], ah1, bl + 4);
                mma_bf16(acc[1][2], al1, bh + 4);
                if (do3) {
                    mma_bf16(acc[1][3], ah1, bh + 6);
                    mma_bf16(acc[1][3], ah1, bl + 6);
                    mma_bf16(acc[1][3], al1, bh + 6);
                }
            }
            // dump at k boundary (transposed [c][b]; sector-dense writes)
            if ((i & 15) == 15) {
                const int k  = i >> 4;
                const int rr = wid * 32 + (lane >> 2);
                const int cb = (lane & 3) * 2;
#pragma unroll
                for (int mt = 0; mt < 2; ++mt) {
#pragma unroll
                    for (int nt = 0; nt < 4; ++nt) {
                        if (k > 0 && nt == 3) continue;
                        const int c = k * 32 + nt * 8 + cb;
                        const int r = b0 + rr + mt * 16;
                        g_qkv[(size_t)c * BB + r]           = acc[mt][nt][0];
                        g_qkv[(size_t)(c + 1) * BB + r]     = acc[mt][nt][1];
                        g_qkv[(size_t)c * BB + r + 8]       = acc[mt][nt][2];
                        g_qkv[(size_t)(c + 1) * BB + r + 8] = acc[mt][nt][3];
#pragma unroll
                        for (int q = 0; q < 4; ++q) acc[mt][nt][q] = 0.f;
                    }
                }
            }
        }

        // va holds A(i+1): convert+store into next buffer, then refill for i+2
        if (hn) convert_sts(smem + BUF_BASE + ((i + 1) & 1) * BUF_SZ, va);
        if (i + 2 < NIT) load_A(i + 2, va);

        CP_WAIT0();
        __syncthreads();
    }

    // ---- phase 2: per-row attention (threads 0..127), attn staged in smem ----
    float* sAttn = (float*)(smem + BUF_BASE);   // 128 rows x 100 floats = 51.2 KB
    if (tid < 128) {
        const int b = b0 + tid;
        const float* sBC = (const float*)(smem + S_BC);

        float q[KK][EE], ke[KK][EE], v0[EE];
#pragma unroll
        for (int k = 0; k < KK; ++k)
#pragma unroll
            for (int e = 0; e < EE; ++e) {
                q[k][e]  = g_qkv[(size_t)(k * 32 + e) * BB + b]      + sBC[k * 32 + e];
                ke[k][e] = g_qkv[(size_t)(k * 32 + 10 + e) * BB + b] + sBC[k * 32 + 10 + e];
            }
#pragma unroll
        for (int e = 0; e < EE; ++e)
            v0[e] = g_qkv[(size_t)(20 + e) * BB + b] + sBC[20 + e];

        float w0o[EE];
#pragma unroll
        for (int e = 0; e < EE; ++e) w0o[e] = 0.f;
        const float inv_sqrtE = 0.31622776601683794f;   // 1/sqrt(10)
        float* arow = sAttn + tid * 100;

#pragma unroll
        for (int l = 0; l < EE; ++l) {
            float col[EE];
#pragma unroll
            for (int e = 0; e < EE; ++e)
                col[e] = (q[0][e] * ke[0][l] + q[1][e] * ke[1][l] +
                          q[2][e] * ke[2][l] + q[3][e] * ke[3][l]) * inv_sqrtE;
            float mx = col[0];
#pragma unroll
            for (int e = 1; e < EE; ++e) mx = fmaxf(mx, col[e]);
            float p[EE], s = 0.f;
#pragma unroll
            for (int e = 0; e < EE; ++e) { p[e] = __expf(col[e] - mx); s += p[e]; }
            const float is = 1.f / s;
#pragma unroll
            for (int e = 0; e < EE; ++e) {
                p[e] *= is;
                arow[e * EE + l] = p[e];
                w0o[e] += p[e] * v0[l];
            }
        }

        float oacc[CC];
#pragma unroll
        for (int c = 0; c < CC; ++c) oacc[c] = 0.f;
#pragma unroll
        for (int k = 0; k < KK; ++k) {
            float lg[CC];
#pragma unroll
            for (int c = 0; c < CC; ++c) {
                float s2 = bfin[k * CC + c];
#pragma unroll
                for (int e = 0; e < EE; ++e)
                    s2 += w0o[e] * Wfin[k * CC * EE + c * EE + e];
                lg[c] = s2;
            }
            float mx = lg[0];
#pragma unroll
            for (int c = 1; c < CC; ++c) mx = fmaxf(mx, lg[c]);
            float p[CC], s = 0.f;
#pragma unroll
            for (int c = 0; c < CC; ++c) { p[c] = __expf(lg[c] - mx); s += p[c]; }
            const float is = 1.f / s;
#pragma unroll
            for (int c = 0; c < CC; ++c) oacc[c] += p[c] * is;
        }
        float* outr = out_outputs + (size_t)b * CC;
#pragma unroll
        for (int c = 0; c < CC; ++c) outr[c] = oacc[c] * 0.25f;
    }
    __syncthreads();

    // dense coalesced attn writeback: 128 rows x 100 floats = 3200 float4
    {
        const float4* src = (const float4*)sAttn;
        float4* dst = (float4*)(out_attn + (size_t)b0 * 100);
        for (int t = tid; t < 3200; t += 256) dst[t] = src[t];
    }
}

// ---------------------------------------------------------------------------
extern "C" void kernel_launch(void* const* d_in, const int* in_sizes, int n_in,
                              void* d_out, int out_size) {
    const float* w0   = (const float*)d_in[0];
    const float* w1   = (const float*)d_in[1];
    const float* w2   = (const float*)d_in[2];
    const float* w3   = (const float*)d_in[3];
    const float* Wlin = (const float*)d_in[4];
    const float* blin = (const float*)d_in[5];
    const float* Wq   = (const float*)d_in[6];
    const float* bq   = (const float*)d_in[7];
    const float* Wk   = (const float*)d_in[8];
    const float* bk   = (const float*)d_in[9];
    const float* Wv   = (const float*)d_in[10];
    const float* bv   = (const float*)d_in[11];
    const float* Wfin = (const float*)d_in[12];
    const float* bfin = (const float*)d_in[13];

    float* out      = (float*)d_out;
    float* out_attn = out + (size_t)BB * CC;

    cudaFuncSetAttribute(fused_main, cudaFuncAttributeMaxDynamicSharedMemorySize, SMEM_BYTES);

    precompute_part<<<dim3(4, 32, 16), 128>>>(Wlin, Wq, Wk, Wv);
    finalize<<<528, 256>>>(blin, Wq, bq, Wk, bk, Wv, bv);
    fused_main<<<BB / 128, 256, SMEM_BYTES>>>(w0, w1, w2, w3, Wfin, bfin, out, out_attn);
}